// round 8
// baseline (speedup 1.0000x reference)
#include <cuda_runtime.h>
#include <cuda_bf16.h>
#include <cuda_fp16.h>
#include <math.h>
#include <stdint.h>

// Problem constants
#define BATCH   2
#define SEQ     2048
#define DMODEL  2048
#define NHEADS  16
#define DHEAD   128
#define MROWS   (BATCH*SEQ)          // 4096
#define QKVDIM  (3*DMODEL)           // 6144
#define KDIM    2048

// Scratch (__device__ globals; allocation-free rule)
__device__ float2 g_rope[(size_t)SEQ * 64];
__device__ __nv_bfloat16 g_xh[(size_t)MROWS * KDIM],   g_xl[(size_t)MROWS * KDIM];
__device__ __nv_bfloat16 g_wqh[(size_t)QKVDIM * KDIM], g_wql[(size_t)QKVDIM * KDIM];
__device__ __nv_bfloat16 g_ah[(size_t)MROWS * KDIM],   g_al[(size_t)MROWS * KDIM];
__device__ __nv_bfloat16 g_wh[(size_t)DMODEL * KDIM],  g_wl[(size_t)DMODEL * KDIM];
// fp16 hi/lo attention operands, [B][H][T][D]
#define NATT ((size_t)BATCH * NHEADS * SEQ * DHEAD)
__device__ __half g_qh16[NATT], g_ql16[NATT];
__device__ __half g_kh16[NATT];
__device__ __half g_vh16[NATT], g_vl16[NATT];

// ---------------------------------------------------------------------------
// PTX helpers
// ---------------------------------------------------------------------------
static __device__ __forceinline__ uint32_t smem_u32(const void* p) {
    uint32_t a;
    asm("{ .reg .u64 t; cvta.to.shared.u64 t, %1; cvt.u32.u64 %0, t; }" : "=r"(a) : "l"(p));
    return a;
}
static __device__ __forceinline__ void cpasync16(uint32_t dst, const void* src) {
    asm volatile("cp.async.cg.shared.global [%0], [%1], 16;\n" :: "r"(dst), "l"(src));
}
#define CP_COMMIT() asm volatile("cp.async.commit_group;\n" ::: "memory")
#define CP_WAIT0()  asm volatile("cp.async.wait_group 0;\n" ::: "memory")
#define CP_WAIT1()  asm volatile("cp.async.wait_group 1;\n" ::: "memory")

static __device__ __forceinline__ void ldsm_x4(uint32_t& r0, uint32_t& r1,
                                               uint32_t& r2, uint32_t& r3, uint32_t a) {
    asm volatile("ldmatrix.sync.aligned.m8n8.x4.shared.b16 {%0,%1,%2,%3}, [%4];"
                 : "=r"(r0), "=r"(r1), "=r"(r2), "=r"(r3) : "r"(a));
}
static __device__ __forceinline__ void ldsm_x4t(uint32_t& r0, uint32_t& r1,
                                                uint32_t& r2, uint32_t& r3, uint32_t a) {
    asm volatile("ldmatrix.sync.aligned.m8n8.x4.trans.shared.b16 {%0,%1,%2,%3}, [%4];"
                 : "=r"(r0), "=r"(r1), "=r"(r2), "=r"(r3) : "r"(a));
}
static __device__ __forceinline__ void mma_bf16(float* c, const uint32_t* a,
                                                uint32_t b0, uint32_t b1) {
    asm volatile(
        "mma.sync.aligned.m16n8k16.row.col.f32.bf16.bf16.f32 "
        "{%0,%1,%2,%3}, {%4,%5,%6,%7}, {%8,%9}, {%0,%1,%2,%3};"
        : "+f"(c[0]), "+f"(c[1]), "+f"(c[2]), "+f"(c[3])
        : "r"(a[0]), "r"(a[1]), "r"(a[2]), "r"(a[3]), "r"(b0), "r"(b1));
}
static __device__ __forceinline__ void mma_f16(float* c, const uint32_t* a,
                                               uint32_t b0, uint32_t b1) {
    asm volatile(
        "mma.sync.aligned.m16n8k16.row.col.f32.f16.f16.f32 "
        "{%0,%1,%2,%3}, {%4,%5,%6,%7}, {%8,%9}, {%0,%1,%2,%3};"
        : "+f"(c[0]), "+f"(c[1]), "+f"(c[2]), "+f"(c[3])
        : "r"(a[0]), "r"(a[1]), "r"(a[2]), "r"(a[3]), "r"(b0), "r"(b1));
}
static __device__ __forceinline__ void pack_hl(float f0, float f1, uint32_t& hi, uint32_t& lo) {
    __half2 h = __floats2half2_rn(f0, f1);
    float2 fb = __half22float2(h);
    __half2 l2 = __floats2half2_rn(f0 - fb.x, f1 - fb.y);
    hi = *reinterpret_cast<uint32_t*>(&h);
    lo = *reinterpret_cast<uint32_t*>(&l2);
}
static __device__ __forceinline__ uint32_t ex2_f16x2(float a, float b) {
    uint32_t d;
    asm("{ .reg .b32 t;\n cvt.rn.f16x2.f32 t, %2, %1;\n ex2.approx.f16x2 %0, t;\n}"
        : "=r"(d) : "f"(a), "f"(b));
    return d;
}

// ---------------------------------------------------------------------------
// fp32 -> bf16 hi/lo split, vectorized x4
// ---------------------------------------------------------------------------
__global__ __launch_bounds__(256) void split_kernel(
    const float4* __restrict__ s, uint2* __restrict__ hi,
    uint2* __restrict__ lo, int n4)
{
    int i = blockIdx.x * 256 + threadIdx.x;
    if (i >= n4) return;
    float4 v = s[i];
    __nv_bfloat162 h01, h23, l01, l23;
    h01.x = __float2bfloat16(v.x); h01.y = __float2bfloat16(v.y);
    h23.x = __float2bfloat16(v.z); h23.y = __float2bfloat16(v.w);
    l01.x = __float2bfloat16(v.x - __bfloat162float(h01.x));
    l01.y = __float2bfloat16(v.y - __bfloat162float(h01.y));
    l23.x = __float2bfloat16(v.z - __bfloat162float(h23.x));
    l23.y = __float2bfloat16(v.w - __bfloat162float(h23.y));
    uint2 hv, lv;
    hv.x = *reinterpret_cast<uint32_t*>(&h01); hv.y = *reinterpret_cast<uint32_t*>(&h23);
    lv.x = *reinterpret_cast<uint32_t*>(&l01); lv.y = *reinterpret_cast<uint32_t*>(&l23);
    hi[i] = hv;
    lo[i] = lv;
}

// ---------------------------------------------------------------------------
// RoPE cos/sin table
// ---------------------------------------------------------------------------
__global__ __launch_bounds__(256) void rope_table_kernel(float2* __restrict__ tab)
{
    int idx = blockIdx.x * 256 + threadIdx.x;
    int i = idx & 63, t = idx >> 6;
    double freq = exp(-9.210340371976184 * (double)(2 * i) / 128.0);
    double sd, cd;
    sincos((double)t * freq, &sd, &cd);
    tab[idx] = make_float2((float)cd, (float)sd);
}

// ---------------------------------------------------------------------------
// GEMM mainloop (NT, bf16 hi/lo 3-term) — round-6 configuration.
// BM=BN=128, BK=32, 256 threads, 8 warps (2m x 4n), warp tile 64x32, occ 2.
// ---------------------------------------------------------------------------
#define BM 128
#define BN 128
#define BK 32
#define SROW 40
#define PART_BYTES (128 * SROW * 2)
#define STG_BYTES  (4 * PART_BYTES)
#define AH_OFF 0
#define AL_OFF PART_BYTES
#define BH_OFF (2 * PART_BYTES)
#define BL_OFF (3 * PART_BYTES)
#define GSMEM (2 * STG_BYTES)

static __device__ __forceinline__ void g_load_stage(
    uint32_t sb, int buf, int s, int bm, int bn, int tid,
    const __nv_bfloat16* __restrict__ Ah, const __nv_bfloat16* __restrict__ Al,
    const __nv_bfloat16* __restrict__ Bh, const __nv_bfloat16* __restrict__ Bl)
{
    uint32_t base = sb + buf * STG_BYTES;
    const int k0 = s * BK;
#pragma unroll
    for (int it = 0; it < 2; it++) {
        int idx = tid + it * 256;
        int r = idx >> 2, ch = idx & 3;
        uint32_t so = r * (SROW * 2) + ch * 16;
        size_t ga = (size_t)(bm + r) * KDIM + k0 + ch * 8;
        size_t gb = (size_t)(bn + r) * KDIM + k0 + ch * 8;
        cpasync16(base + AH_OFF + so, Ah + ga);
        cpasync16(base + AL_OFF + so, Al + ga);
        cpasync16(base + BH_OFF + so, Bh + gb);
        cpasync16(base + BL_OFF + so, Bl + gb);
    }
    CP_COMMIT();
}

static __device__ __forceinline__ void g_mainloop(
    uint32_t sb, int bm, int bn, int tid, int lane, int wm, int wn,
    const __nv_bfloat16* __restrict__ Ah, const __nv_bfloat16* __restrict__ Al,
    const __nv_bfloat16* __restrict__ Bh, const __nv_bfloat16* __restrict__ Bl,
    float acc[4][4][4])
{
    const uint32_t aRow = wm * 64 + (lane & 15);
    const uint32_t aCol = (lane >> 4) << 3;
    const uint32_t bOff = (wn * 32 + (lane & 7) + ((lane & 16) >> 1)) * (SROW * 2)
                        + (((lane >> 3) & 1) << 3) * 2;

    g_load_stage(sb, 0, 0, bm, bn, tid, Ah, Al, Bh, Bl);

    const int NS = KDIM / BK;
    for (int s = 0; s < NS; s++) {
        const int buf = s & 1;
        if (s + 1 < NS) {
            g_load_stage(sb, buf ^ 1, s + 1, bm, bn, tid, Ah, Al, Bh, Bl);
            CP_WAIT1();
        } else {
            CP_WAIT0();
        }
        __syncthreads();

        uint32_t base = sb + buf * STG_BYTES;
#pragma unroll
        for (int kk = 0; kk < BK; kk += 16) {
            uint32_t af[4][4], bh[4][2], bl[4][2];
#pragma unroll
            for (int mt = 0; mt < 4; mt++)
                ldsm_x4(af[mt][0], af[mt][1], af[mt][2], af[mt][3],
                        base + AH_OFF + (aRow + mt * 16) * (SROW * 2) + (aCol + kk) * 2);
#pragma unroll
            for (int np = 0; np < 2; np++) {
                ldsm_x4(bh[2*np][0], bh[2*np][1], bh[2*np+1][0], bh[2*np+1][1],
                        base + BH_OFF + bOff + np * 16 * (SROW * 2) + kk * 2);
                ldsm_x4(bl[2*np][0], bl[2*np][1], bl[2*np+1][0], bl[2*np+1][1],
                        base + BL_OFF + bOff + np * 16 * (SROW * 2) + kk * 2);
            }
            // Ah x Bh
#pragma unroll
            for (int mt = 0; mt < 4; mt++)
#pragma unroll
                for (int nt = 0; nt < 4; nt++)
                    mma_bf16(acc[mt][nt], af[mt], bh[nt][0], bh[nt][1]);
            // Ah x Bl
#pragma unroll
            for (int mt = 0; mt < 4; mt++)
#pragma unroll
                for (int nt = 0; nt < 4; nt++)
                    mma_bf16(acc[mt][nt], af[mt], bl[nt][0], bl[nt][1]);
            // Al x Bh
#pragma unroll
            for (int mt = 0; mt < 4; mt++)
                ldsm_x4(af[mt][0], af[mt][1], af[mt][2], af[mt][3],
                        base + AL_OFF + (aRow + mt * 16) * (SROW * 2) + (aCol + kk) * 2);
#pragma unroll
            for (int mt = 0; mt < 4; mt++)
#pragma unroll
                for (int nt = 0; nt < 4; nt++)
                    mma_bf16(acc[mt][nt], af[mt], bh[nt][0], bh[nt][1]);
        }
        __syncthreads();
    }
}

// Plain fp32-output GEMM (WO projection)
__global__ __launch_bounds__(256, 2) void gemm_mma(
    const __nv_bfloat16* __restrict__ Ah, const __nv_bfloat16* __restrict__ Al,
    const __nv_bfloat16* __restrict__ Bh, const __nv_bfloat16* __restrict__ Bl,
    float* __restrict__ C, int ldc)
{
    extern __shared__ char smem[];
    uint32_t sb = smem_u32(smem);
    const int tid = threadIdx.x, wid = tid >> 5, lane = tid & 31;
    const int wm = wid >> 2, wn = wid & 3;
    const int bm = blockIdx.y * BM, bn = blockIdx.x * BN;

    float acc[4][4][4];
#pragma unroll
    for (int i = 0; i < 4; i++)
#pragma unroll
        for (int j = 0; j < 4; j++)
#pragma unroll
            for (int e = 0; e < 4; e++) acc[i][j][e] = 0.f;

    g_mainloop(sb, bm, bn, tid, lane, wm, wn, Ah, Al, Bh, Bl, acc);

    const int r0 = bm + wm * 64 + (lane >> 2);
    const int c0 = bn + wn * 32 + 2 * (lane & 3);
#pragma unroll
    for (int mt = 0; mt < 4; mt++)
#pragma unroll
        for (int nt = 0; nt < 4; nt++) {
            float2 v0 = make_float2(acc[mt][nt][0], acc[mt][nt][1]);
            float2 v1 = make_float2(acc[mt][nt][2], acc[mt][nt][3]);
            *reinterpret_cast<float2*>(&C[(size_t)(r0 + mt * 16)     * ldc + c0 + nt * 8]) = v0;
            *reinterpret_cast<float2*>(&C[(size_t)(r0 + mt * 16 + 8) * ldc + c0 + nt * 8]) = v1;
        }
}

// QKV GEMM with fused RoPE + fp16 hi/lo pack + [B,H,T,D] transpose epilogue.
__global__ __launch_bounds__(256, 2) void gemm_qkv(
    const __nv_bfloat16* __restrict__ Ah, const __nv_bfloat16* __restrict__ Al,
    const __nv_bfloat16* __restrict__ Bh, const __nv_bfloat16* __restrict__ Bl,
    const float2* __restrict__ tab,
    __half* __restrict__ Qh, __half* __restrict__ Ql,
    __half* __restrict__ Kh,
    __half* __restrict__ Vh, __half* __restrict__ Vl)
{
    extern __shared__ char smem[];
    uint32_t sb = smem_u32(smem);
    const int tid = threadIdx.x, wid = tid >> 5, lane = tid & 31;
    const int wm = wid >> 2, wn = wid & 3;
    const int bm = blockIdx.y * BM, bn = blockIdx.x * BN;

    float acc[4][4][4];
#pragma unroll
    for (int i = 0; i < 4; i++)
#pragma unroll
        for (int j = 0; j < 4; j++)
#pragma unroll
            for (int e = 0; e < 4; e++) acc[i][j][e] = 0.f;

    g_mainloop(sb, bm, bn, tid, lane, wm, wn, Ah, Al, Bh, Bl, acc);

    const int mat  = bn >> 11;                  // 0=Q,1=K,2=V
    const int head = (bn >> 7) & (NHEADS - 1);
    const float QSCL = 0.1275174456f;           // log2(e)/sqrt(128)

    const int r0 = bm + wm * 64 + (lane >> 2);
    const int c0 = (bn & 127) + wn * 32 + 2 * (lane & 3);
    const int b  = r0 >> 11;
    const size_t obase = ((size_t)(b * NHEADS + head)) * SEQ * DHEAD;

#pragma unroll
    for (int mt = 0; mt < 4; mt++) {
        const int tA = (r0 + mt * 16) & (SEQ - 1);
        const int tB = tA + 8;
#pragma unroll
        for (int nt = 0; nt < 4; nt++) {
            const int d = c0 + nt * 8;
            float x0 = acc[mt][nt][0], x1 = acc[mt][nt][1];
            float y0 = acc[mt][nt][2], y1 = acc[mt][nt][3];
            if (mat < 2) {
                float2 csA = tab[tA * 64 + (d >> 1)];
                float2 csB = tab[tB * 64 + (d >> 1)];
                float nx0 = x0 * csA.x - x1 * csA.y;
                float nx1 = x1 * csA.x + x0 * csA.y;
                float ny0 = y0 * csB.x - y1 * csB.y;
                float ny1 = y1 * csB.x + y0 * csB.y;
                x0 = nx0; x1 = nx1; y0 = ny0; y1 = ny1;
                if (mat == 0) { x0 *= QSCL; x1 *= QSCL; y0 *= QSCL; y1 *= QSCL; }
            }
            size_t dA = obase + (size_t)tA * DHEAD + d;
            size_t dB = obase + (size_t)tB * DHEAD + d;
            uint32_t hi, lo;
            if (mat == 0) {
                pack_hl(x0, x1, hi, lo);
                *reinterpret_cast<uint32_t*>(Qh + dA) = hi;
                *reinterpret_cast<uint32_t*>(Ql + dA) = lo;
                pack_hl(y0, y1, hi, lo);
                *reinterpret_cast<uint32_t*>(Qh + dB) = hi;
                *reinterpret_cast<uint32_t*>(Ql + dB) = lo;
            } else if (mat == 1) {
                __half2 k0 = __floats2half2_rn(x0, x1);
                __half2 k1 = __floats2half2_rn(y0, y1);
                *reinterpret_cast<__half2*>(Kh + dA) = k0;
                *reinterpret_cast<__half2*>(Kh + dB) = k1;
            } else {
                pack_hl(x0, x1, hi, lo);
                *reinterpret_cast<uint32_t*>(Vh + dA) = hi;
                *reinterpret_cast<uint32_t*>(Vl + dA) = lo;
                pack_hl(y0, y1, hi, lo);
                *reinterpret_cast<uint32_t*>(Vh + dB) = hi;
                *reinterpret_cast<uint32_t*>(Vl + dB) = lo;
            }
        }
    }
}

// ---------------------------------------------------------------------------
// Flash attention. TQ=128, TK=64, 8 warps. Triple-buffered KV, ONE barrier
// per k-tile (sync at top of iter kt proves all warps finished kt-1, whose
// buffer (kt-1)%3 == (kt+2)%3 is the one the new prefetch overwrites).
// ---------------------------------------------------------------------------
#define AT_SROWB 272
#define SM_QH 0
#define SM_QL 34816
#define SM_KV 69632
#define KPART 17408
#define KVSTRIDE (3 * KPART)            // Kh|Vh|Vl per buffer = 52224
#define AT_SMEM (SM_KV + 3 * KVSTRIDE)  // 226304

static __device__ __forceinline__ void at_load_kv(
    uint32_t sb, int buf, int kt, size_t bh, int tid,
    const __half* __restrict__ Kh,
    const __half* __restrict__ Vh, const __half* __restrict__ Vl)
{
    const int k0 = kt * 64;
#pragma unroll
    for (int it = 0; it < 12; it++) {
        int idx = tid + it * 256;
        int part = idx >> 10;               // 0:Kh 1:Vh 2:Vl
        int rem = idx & 1023;
        int r = rem >> 4, ch = rem & 15;
        const __half* src = (part == 0) ? Kh : (part == 1) ? Vh : Vl;
        uint32_t dbase = SM_KV + buf * KVSTRIDE + part * KPART;
        cpasync16(sb + dbase + r * AT_SROWB + ch * 16,
                  src + ((size_t)(bh + k0 + r)) * DHEAD + ch * 8);
    }
    CP_COMMIT();
}

__global__ __launch_bounds__(256, 1) void attn_mma(
    const __half* __restrict__ Qh, const __half* __restrict__ Ql,
    const __half* __restrict__ Kh,
    const __half* __restrict__ Vh, const __half* __restrict__ Vl,
    __nv_bfloat16* __restrict__ Oh, __nv_bfloat16* __restrict__ Ol)
{
    extern __shared__ char smem[];
    uint32_t sb = smem_u32(smem);
    const int tid = threadIdx.x, lane = tid & 31, w = tid >> 5;
    const int qt = gridDim.x - 1 - blockIdx.x;
    const int h = blockIdx.y, b = blockIdx.z;
    const int q0 = qt * 128;
    const size_t bh = (size_t)(b * NHEADS + h) * SEQ;

    // Q load (own commit group; retires before kv0 per in-order retirement)
    {
        const __half* gq0 = Qh + (bh + q0) * DHEAD;
        const __half* gq1 = Ql + (bh + q0) * DHEAD;
#pragma unroll
        for (int it = 0; it < 16; it++) {
            int idx = tid + it * 256;
            int part = idx >> 11, rem = idx & 2047;
            int r = rem >> 4, ch = rem & 15;
            const __half* src = part ? gq1 : gq0;
            cpasync16(sb + SM_QH + part * 34816 + r * AT_SROWB + ch * 16,
                      src + (size_t)r * DHEAD + ch * 8);
        }
        CP_COMMIT();
    }

    const int nkt = 2 * qt + 2;
    at_load_kv(sb, 0, 0, bh, tid, Kh, Vh, Vl);
    at_load_kv(sb, 1, 1, bh, tid, Kh, Vh, Vl);

    float m[2] = {-1e30f, -1e30f}, l[2] = {0.f, 0.f};
    float O[16][4];
#pragma unroll
    for (int i = 0; i < 16; i++)
#pragma unroll
        for (int e = 0; e < 4; e++) O[i][e] = 0.f;

    const uint32_t qha = sb + SM_QH + (w * 16 + (lane & 15)) * AT_SROWB + (((uint32_t)lane >> 4) << 3) * 2;
    const uint32_t qla = qha + 34816;
    const uint32_t koff = ((lane & 7) + ((lane & 16) >> 1)) * AT_SROWB + (((lane >> 3) & 1) << 3) * 2;
    const uint32_t voff = (lane & 15) * AT_SROWB + (((uint32_t)lane >> 4) << 3) * 2;
    const uint32_t ONES = 0x3C003C00u;

    int buf = 0;
    for (int kt = 0; kt < nkt; kt++) {
        if (kt + 1 < nkt) { CP_WAIT1(); } else { CP_WAIT0(); }
        __syncthreads();                     // kt resident; buffer (kt+2)%3 free
        if (kt + 2 < nkt) {
            int nbuf = buf + 2; if (nbuf >= 3) nbuf -= 3;
            at_load_kv(sb, nbuf, kt + 2, bh, tid, Kh, Vh, Vl);
        }

        // ---- S = Q K^T (2-term: Qh*Kh + Ql*Kh) ----
        float sacc[8][4];
#pragma unroll
        for (int nt = 0; nt < 8; nt++)
#pragma unroll
            for (int e = 0; e < 4; e++) sacc[nt][e] = 0.f;

        const uint32_t kbase = sb + SM_KV + buf * KVSTRIDE;
#pragma unroll
        for (int ks = 0; ks < 8; ks++) {
            uint32_t qh[4], ql[4];
            ldsm_x4(qh[0], qh[1], qh[2], qh[3], qha + ks * 32);
            ldsm_x4(ql[0], ql[1], ql[2], ql[3], qla + ks * 32);
#pragma unroll
            for (int np = 0; np < 4; np++) {
                uint32_t k0r, k1r, k2r, k3r;
                ldsm_x4(k0r, k1r, k2r, k3r,
                        kbase + koff + np * 16 * AT_SROWB + ks * 32);
                mma_f16(sacc[2*np],   qh, k0r, k1r);
                mma_f16(sacc[2*np],   ql, k0r, k1r);
                mma_f16(sacc[2*np+1], qh, k2r, k3r);
                mma_f16(sacc[2*np+1], ql, k2r, k3r);
            }
        }

        // ---- causal mask (diagonal tiles only) ----
        const int k0 = kt * 64;
        if (k0 + 63 > q0 + w * 16) {
            const int rA = q0 + w * 16 + (lane >> 2);
#pragma unroll
            for (int nt = 0; nt < 8; nt++) {
                int c = k0 + nt * 8 + 2 * (lane & 3);
                if (c     > rA)     sacc[nt][0] = -1e30f;
                if (c + 1 > rA)     sacc[nt][1] = -1e30f;
                if (c     > rA + 8) sacc[nt][2] = -1e30f;
                if (c + 1 > rA + 8) sacc[nt][3] = -1e30f;
            }
        }

        // ---- online softmax (log2 units) ----
        float mx0 = sacc[0][0], mx1 = sacc[0][2];
#pragma unroll
        for (int nt = 0; nt < 8; nt++) {
            mx0 = fmaxf(mx0, fmaxf(sacc[nt][0], sacc[nt][1]));
            mx1 = fmaxf(mx1, fmaxf(sacc[nt][2], sacc[nt][3]));
        }
        mx0 = fmaxf(mx0, __shfl_xor_sync(0xffffffffu, mx0, 1));
        mx0 = fmaxf(mx0, __shfl_xor_sync(0xffffffffu, mx0, 2));
        mx1 = fmaxf(mx1, __shfl_xor_sync(0xffffffffu, mx1, 1));
        mx1 = fmaxf(mx1, __shfl_xor_sync(0xffffffffu, mx1, 2));
        const float mn0 = fmaxf(m[0], mx0), mn1 = fmaxf(m[1], mx1);
        const float fac0 = exp2f(m[0] - mn0), fac1 = exp2f(m[1] - mn1);
        m[0] = mn0; m[1] = mn1;

        // ---- P = 2^(s - mn) as fp16 A-fragments ----
        uint32_t aPh[4][4];
#pragma unroll
        for (int ks = 0; ks < 4; ks++) {
            aPh[ks][0] = ex2_f16x2(sacc[2*ks][0]   - mn0, sacc[2*ks][1]   - mn0);
            aPh[ks][1] = ex2_f16x2(sacc[2*ks][2]   - mn1, sacc[2*ks][3]   - mn1);
            aPh[ks][2] = ex2_f16x2(sacc[2*ks+1][0] - mn0, sacc[2*ks+1][1] - mn0);
            aPh[ks][3] = ex2_f16x2(sacc[2*ks+1][2] - mn1, sacc[2*ks+1][3] - mn1);
        }

        // ---- rescale O; O += P V (2-term); l via ones-mma ----
#pragma unroll
        for (int i = 0; i < 16; i++) {
            O[i][0] *= fac0; O[i][1] *= fac0;
            O[i][2] *= fac1; O[i][3] *= fac1;
        }
        float Olsum[4] = {0.f, 0.f, 0.f, 0.f};
        const uint32_t vbase = kbase + KPART;
#pragma unroll
        for (int ks = 0; ks < 4; ks++) {
            mma_f16(Olsum, aPh[ks], ONES, ONES);
#pragma unroll
            for (int dt = 0; dt < 8; dt++) {
                uint32_t va = vbase + voff + ks * 16 * AT_SROWB + dt * 32;
                uint32_t vh0, vh1, vh2, vh3, vl0, vl1, vl2, vl3;
                ldsm_x4t(vh0, vh1, vh2, vh3, va);
                ldsm_x4t(vl0, vl1, vl2, vl3, va + KPART);
                mma_f16(O[2*dt],   aPh[ks], vh0, vh1);
                mma_f16(O[2*dt+1], aPh[ks], vh2, vh3);
                mma_f16(O[2*dt],   aPh[ks], vl0, vl1);
                mma_f16(O[2*dt+1], aPh[ks], vl2, vl3);
            }
        }
        l[0] = l[0] * fac0 + Olsum[0];
        l[1] = l[1] * fac1 + Olsum[2];

        buf++; if (buf >= 3) buf = 0;
    }

    // ---- normalize & write bf16 hi/lo ----
    const float inv0 = 1.f / l[0], inv1 = 1.f / l[1];
    const int rowA = q0 + w * 16 + (lane >> 2);
    const size_t baseA = ((size_t)b * SEQ + rowA) * DMODEL + h * DHEAD;
    const size_t baseB = baseA + (size_t)8 * DMODEL;
#pragma unroll
    for (int nt = 0; nt < 16; nt++) {
        int d = nt * 8 + 2 * (lane & 3);
        float o0 = O[nt][0] * inv0, o1 = O[nt][1] * inv0;
        float o2 = O[nt][2] * inv1, o3 = O[nt][3] * inv1;
        __nv_bfloat162 h0, l0h, h2, l2h;
        h0.x = __float2bfloat16(o0); h0.y = __float2bfloat16(o1);
        l0h.x = __float2bfloat16(o0 - __bfloat162float(h0.x));
        l0h.y = __float2bfloat16(o1 - __bfloat162float(h0.y));
        h2.x = __float2bfloat16(o2); h2.y = __float2bfloat16(o3);
        l2h.x = __float2bfloat16(o2 - __bfloat162float(h2.x));
        l2h.y = __float2bfloat16(o3 - __bfloat162float(h2.y));
        *reinterpret_cast<__nv_bfloat162*>(Oh + baseA + d) = h0;
        *reinterpret_cast<__nv_bfloat162*>(Ol + baseA + d) = l0h;
        *reinterpret_cast<__nv_bfloat162*>(Oh + baseB + d) = h2;
        *reinterpret_cast<__nv_bfloat162*>(Ol + baseB + d) = l2h;
    }
}

// ---------------------------------------------------------------------------
extern "C" void kernel_launch(void* const* d_in, const int* in_sizes, int n_in,
                              void* d_out, int out_size)
{
    const float* x    = (const float*)d_in[0];
    const float* Wqkv = (const float*)d_in[1];
    const float* WO   = (const float*)d_in[2];
    float* out = (float*)d_out;

    float2* rope;
    cudaGetSymbolAddress((void**)&rope, g_rope);
    __nv_bfloat16 *xh, *xl, *wqh, *wql, *ah, *al, *wh, *wl;
    cudaGetSymbolAddress((void**)&xh, g_xh);   cudaGetSymbolAddress((void**)&xl, g_xl);
    cudaGetSymbolAddress((void**)&wqh, g_wqh); cudaGetSymbolAddress((void**)&wql, g_wql);
    cudaGetSymbolAddress((void**)&ah, g_ah);   cudaGetSymbolAddress((void**)&al, g_al);
    cudaGetSymbolAddress((void**)&wh, g_wh);   cudaGetSymbolAddress((void**)&wl, g_wl);
    __half *qh16, *ql16, *kh16, *vh16, *vl16;
    cudaGetSymbolAddress((void**)&qh16, g_qh16); cudaGetSymbolAddress((void**)&ql16, g_ql16);
    cudaGetSymbolAddress((void**)&kh16, g_kh16);
    cudaGetSymbolAddress((void**)&vh16, g_vh16); cudaGetSymbolAddress((void**)&vl16, g_vl16);

    cudaFuncSetAttribute(gemm_mma, cudaFuncAttributeMaxDynamicSharedMemorySize, GSMEM);
    cudaFuncSetAttribute(gemm_qkv, cudaFuncAttributeMaxDynamicSharedMemorySize, GSMEM);
    cudaFuncSetAttribute(attn_mma, cudaFuncAttributeMaxDynamicSharedMemorySize, AT_SMEM);

    rope_table_kernel<<<(SEQ * 64) / 256, 256>>>(rope);
    { int n4 = (MROWS * KDIM) / 4;
      split_kernel<<<(n4 + 255) / 256, 256>>>((const float4*)x, (uint2*)xh, (uint2*)xl, n4); }
    { int n4 = (QKVDIM * KDIM) / 4;
      split_kernel<<<(n4 + 255) / 256, 256>>>((const float4*)Wqkv, (uint2*)wqh, (uint2*)wql, n4); }
    { int n4 = (DMODEL * KDIM) / 4;
      split_kernel<<<(n4 + 255) / 256, 256>>>((const float4*)WO, (uint2*)wh, (uint2*)wl, n4); }

    // 1) QKV GEMM with fused RoPE + fp16 pack + [B,H,T,D] transpose
    {
        dim3 grid(QKVDIM / BN, MROWS / BM);
        gemm_qkv<<<grid, 256, GSMEM>>>(xh, xl, wqh, wql, rope,
                                       qh16, ql16, kh16, vh16, vl16);
    }

    // 2) flash attention -> bf16 hi/lo (ah, al)
    {
        dim3 grid(SEQ / 128, NHEADS, BATCH);
        attn_mma<<<grid, 256, AT_SMEM>>>(qh16, ql16, kh16, vh16, vl16, ah, al);
    }

    // 3) out = att @ WO^T
    {
        dim3 grid(DMODEL / BN, MROWS / BM);
        gemm_mma<<<grid, 256, GSMEM>>>(ah, al, wh, wl, out, DMODEL);
    }
}

// round 9
// speedup vs baseline: 1.5397x; 1.5397x over previous
#include <cuda_runtime.h>
#include <cuda_bf16.h>
#include <cuda_fp16.h>
#include <math.h>
#include <stdint.h>

// Problem constants
#define BATCH   2
#define SEQ     2048
#define DMODEL  2048
#define NHEADS  16
#define DHEAD   128
#define MROWS   (BATCH*SEQ)          // 4096
#define QKVDIM  (3*DMODEL)           // 6144
#define KDIM    2048

// Scratch (__device__ globals; allocation-free rule)
__device__ float2 g_rope[(size_t)SEQ * 64];
__device__ __nv_bfloat16 g_xh[(size_t)MROWS * KDIM],   g_xl[(size_t)MROWS * KDIM];
__device__ __nv_bfloat16 g_wqh[(size_t)QKVDIM * KDIM], g_wql[(size_t)QKVDIM * KDIM];
__device__ __nv_bfloat16 g_ah[(size_t)MROWS * KDIM],   g_al[(size_t)MROWS * KDIM];
__device__ __nv_bfloat16 g_wh[(size_t)DMODEL * KDIM],  g_wl[(size_t)DMODEL * KDIM];
// fp16 hi/lo attention operands, [B][H][T][D]
#define NATT ((size_t)BATCH * NHEADS * SEQ * DHEAD)
__device__ __half g_qh16[NATT], g_ql16[NATT];
__device__ __half g_kh16[NATT];
__device__ __half g_vh16[NATT], g_vl16[NATT];

// ---------------------------------------------------------------------------
// PTX helpers
// ---------------------------------------------------------------------------
static __device__ __forceinline__ uint32_t smem_u32(const void* p) {
    uint32_t a;
    asm("{ .reg .u64 t; cvta.to.shared.u64 t, %1; cvt.u32.u64 %0, t; }" : "=r"(a) : "l"(p));
    return a;
}
static __device__ __forceinline__ void cpasync16(uint32_t dst, const void* src) {
    asm volatile("cp.async.cg.shared.global [%0], [%1], 16;\n" :: "r"(dst), "l"(src));
}
#define CP_COMMIT() asm volatile("cp.async.commit_group;\n" ::: "memory")
#define CP_WAIT0()  asm volatile("cp.async.wait_group 0;\n" ::: "memory")
#define CP_WAIT1()  asm volatile("cp.async.wait_group 1;\n" ::: "memory")

static __device__ __forceinline__ void ldsm_x4(uint32_t& r0, uint32_t& r1,
                                               uint32_t& r2, uint32_t& r3, uint32_t a) {
    asm volatile("ldmatrix.sync.aligned.m8n8.x4.shared.b16 {%0,%1,%2,%3}, [%4];"
                 : "=r"(r0), "=r"(r1), "=r"(r2), "=r"(r3) : "r"(a));
}
static __device__ __forceinline__ void ldsm_x4t(uint32_t& r0, uint32_t& r1,
                                                uint32_t& r2, uint32_t& r3, uint32_t a) {
    asm volatile("ldmatrix.sync.aligned.m8n8.x4.trans.shared.b16 {%0,%1,%2,%3}, [%4];"
                 : "=r"(r0), "=r"(r1), "=r"(r2), "=r"(r3) : "r"(a));
}
static __device__ __forceinline__ void mma_bf16(float* c, const uint32_t* a,
                                                uint32_t b0, uint32_t b1) {
    asm volatile(
        "mma.sync.aligned.m16n8k16.row.col.f32.bf16.bf16.f32 "
        "{%0,%1,%2,%3}, {%4,%5,%6,%7}, {%8,%9}, {%0,%1,%2,%3};"
        : "+f"(c[0]), "+f"(c[1]), "+f"(c[2]), "+f"(c[3])
        : "r"(a[0]), "r"(a[1]), "r"(a[2]), "r"(a[3]), "r"(b0), "r"(b1));
}
static __device__ __forceinline__ void mma_f16(float* c, const uint32_t* a,
                                               uint32_t b0, uint32_t b1) {
    asm volatile(
        "mma.sync.aligned.m16n8k16.row.col.f32.f16.f16.f32 "
        "{%0,%1,%2,%3}, {%4,%5,%6,%7}, {%8,%9}, {%0,%1,%2,%3};"
        : "+f"(c[0]), "+f"(c[1]), "+f"(c[2]), "+f"(c[3])
        : "r"(a[0]), "r"(a[1]), "r"(a[2]), "r"(a[3]), "r"(b0), "r"(b1));
}
static __device__ __forceinline__ void pack_hl(float f0, float f1, uint32_t& hi, uint32_t& lo) {
    __half2 h = __floats2half2_rn(f0, f1);
    float2 fb = __half22float2(h);
    __half2 l2 = __floats2half2_rn(f0 - fb.x, f1 - fb.y);
    hi = *reinterpret_cast<uint32_t*>(&h);
    lo = *reinterpret_cast<uint32_t*>(&l2);
}
static __device__ __forceinline__ uint32_t ex2_f16x2(float a, float b) {
    uint32_t d;
    asm("{ .reg .b32 t;\n cvt.rn.f16x2.f32 t, %2, %1;\n ex2.approx.f16x2 %0, t;\n}"
        : "=r"(d) : "f"(a), "f"(b));
    return d;
}

// ---------------------------------------------------------------------------
// fp32 -> bf16 hi/lo split, vectorized x4 (measured faster than scalar)
// ---------------------------------------------------------------------------
__global__ __launch_bounds__(256) void split_kernel(
    const float4* __restrict__ s, uint2* __restrict__ hi,
    uint2* __restrict__ lo, int n4)
{
    int i = blockIdx.x * 256 + threadIdx.x;
    if (i >= n4) return;
    float4 v = s[i];
    __nv_bfloat162 h01, h23, l01, l23;
    h01.x = __float2bfloat16(v.x); h01.y = __float2bfloat16(v.y);
    h23.x = __float2bfloat16(v.z); h23.y = __float2bfloat16(v.w);
    l01.x = __float2bfloat16(v.x - __bfloat162float(h01.x));
    l01.y = __float2bfloat16(v.y - __bfloat162float(h01.y));
    l23.x = __float2bfloat16(v.z - __bfloat162float(h23.x));
    l23.y = __float2bfloat16(v.w - __bfloat162float(h23.y));
    uint2 hv, lv;
    hv.x = *reinterpret_cast<uint32_t*>(&h01); hv.y = *reinterpret_cast<uint32_t*>(&h23);
    lv.x = *reinterpret_cast<uint32_t*>(&l01); lv.y = *reinterpret_cast<uint32_t*>(&l23);
    hi[i] = hv;
    lo[i] = lv;
}

// ---------------------------------------------------------------------------
// RoPE cos/sin table
// ---------------------------------------------------------------------------
__global__ __launch_bounds__(256) void rope_table_kernel(float2* __restrict__ tab)
{
    int idx = blockIdx.x * 256 + threadIdx.x;
    int i = idx & 63, t = idx >> 6;
    double freq = exp(-9.210340371976184 * (double)(2 * i) / 128.0);
    double sd, cd;
    sincos((double)t * freq, &sd, &cd);
    tab[idx] = make_float2((float)cd, (float)sd);
}

// ---------------------------------------------------------------------------
// GEMM mainloop (NT, bf16 hi/lo 3-term) — round-6 configuration (best).
// BM=BN=128, BK=32, 256 threads, 8 warps (2m x 4n), warp tile 64x32, occ 2.
// ---------------------------------------------------------------------------
#define BM 128
#define BN 128
#define BK 32
#define SROW 40
#define PART_BYTES (128 * SROW * 2)
#define STG_BYTES  (4 * PART_BYTES)
#define AH_OFF 0
#define AL_OFF PART_BYTES
#define BH_OFF (2 * PART_BYTES)
#define BL_OFF (3 * PART_BYTES)
#define GSMEM (2 * STG_BYTES)

static __device__ __forceinline__ void g_load_stage(
    uint32_t sb, int buf, int s, int bm, int bn, int tid,
    const __nv_bfloat16* __restrict__ Ah, const __nv_bfloat16* __restrict__ Al,
    const __nv_bfloat16* __restrict__ Bh, const __nv_bfloat16* __restrict__ Bl)
{
    uint32_t base = sb + buf * STG_BYTES;
    const int k0 = s * BK;
#pragma unroll
    for (int it = 0; it < 2; it++) {
        int idx = tid + it * 256;
        int r = idx >> 2, ch = idx & 3;
        uint32_t so = r * (SROW * 2) + ch * 16;
        size_t ga = (size_t)(bm + r) * KDIM + k0 + ch * 8;
        size_t gb = (size_t)(bn + r) * KDIM + k0 + ch * 8;
        cpasync16(base + AH_OFF + so, Ah + ga);
        cpasync16(base + AL_OFF + so, Al + ga);
        cpasync16(base + BH_OFF + so, Bh + gb);
        cpasync16(base + BL_OFF + so, Bl + gb);
    }
    CP_COMMIT();
}

static __device__ __forceinline__ void g_mainloop(
    uint32_t sb, int bm, int bn, int tid, int lane, int wm, int wn,
    const __nv_bfloat16* __restrict__ Ah, const __nv_bfloat16* __restrict__ Al,
    const __nv_bfloat16* __restrict__ Bh, const __nv_bfloat16* __restrict__ Bl,
    float acc[4][4][4])
{
    const uint32_t aRow = wm * 64 + (lane & 15);
    const uint32_t aCol = (lane >> 4) << 3;
    const uint32_t bOff = (wn * 32 + (lane & 7) + ((lane & 16) >> 1)) * (SROW * 2)
                        + (((lane >> 3) & 1) << 3) * 2;

    g_load_stage(sb, 0, 0, bm, bn, tid, Ah, Al, Bh, Bl);

    const int NS = KDIM / BK;
    for (int s = 0; s < NS; s++) {
        const int buf = s & 1;
        if (s + 1 < NS) {
            g_load_stage(sb, buf ^ 1, s + 1, bm, bn, tid, Ah, Al, Bh, Bl);
            CP_WAIT1();
        } else {
            CP_WAIT0();
        }
        __syncthreads();

        uint32_t base = sb + buf * STG_BYTES;
#pragma unroll
        for (int kk = 0; kk < BK; kk += 16) {
            uint32_t af[4][4], bh[4][2], bl[4][2];
#pragma unroll
            for (int mt = 0; mt < 4; mt++)
                ldsm_x4(af[mt][0], af[mt][1], af[mt][2], af[mt][3],
                        base + AH_OFF + (aRow + mt * 16) * (SROW * 2) + (aCol + kk) * 2);
#pragma unroll
            for (int np = 0; np < 2; np++) {
                ldsm_x4(bh[2*np][0], bh[2*np][1], bh[2*np+1][0], bh[2*np+1][1],
                        base + BH_OFF + bOff + np * 16 * (SROW * 2) + kk * 2);
                ldsm_x4(bl[2*np][0], bl[2*np][1], bl[2*np+1][0], bl[2*np+1][1],
                        base + BL_OFF + bOff + np * 16 * (SROW * 2) + kk * 2);
            }
            // Ah x Bh
#pragma unroll
            for (int mt = 0; mt < 4; mt++)
#pragma unroll
                for (int nt = 0; nt < 4; nt++)
                    mma_bf16(acc[mt][nt], af[mt], bh[nt][0], bh[nt][1]);
            // Ah x Bl
#pragma unroll
            for (int mt = 0; mt < 4; mt++)
#pragma unroll
                for (int nt = 0; nt < 4; nt++)
                    mma_bf16(acc[mt][nt], af[mt], bl[nt][0], bl[nt][1]);
            // Al x Bh
#pragma unroll
            for (int mt = 0; mt < 4; mt++)
                ldsm_x4(af[mt][0], af[mt][1], af[mt][2], af[mt][3],
                        base + AL_OFF + (aRow + mt * 16) * (SROW * 2) + (aCol + kk) * 2);
#pragma unroll
            for (int mt = 0; mt < 4; mt++)
#pragma unroll
                for (int nt = 0; nt < 4; nt++)
                    mma_bf16(acc[mt][nt], af[mt], bh[nt][0], bh[nt][1]);
        }
        __syncthreads();
    }
}

// Plain fp32-output GEMM (WO projection)
__global__ __launch_bounds__(256, 2) void gemm_mma(
    const __nv_bfloat16* __restrict__ Ah, const __nv_bfloat16* __restrict__ Al,
    const __nv_bfloat16* __restrict__ Bh, const __nv_bfloat16* __restrict__ Bl,
    float* __restrict__ C, int ldc)
{
    extern __shared__ char smem[];
    uint32_t sb = smem_u32(smem);
    const int tid = threadIdx.x, wid = tid >> 5, lane = tid & 31;
    const int wm = wid >> 2, wn = wid & 3;
    const int bm = blockIdx.y * BM, bn = blockIdx.x * BN;

    float acc[4][4][4];
#pragma unroll
    for (int i = 0; i < 4; i++)
#pragma unroll
        for (int j = 0; j < 4; j++)
#pragma unroll
            for (int e = 0; e < 4; e++) acc[i][j][e] = 0.f;

    g_mainloop(sb, bm, bn, tid, lane, wm, wn, Ah, Al, Bh, Bl, acc);

    const int r0 = bm + wm * 64 + (lane >> 2);
    const int c0 = bn + wn * 32 + 2 * (lane & 3);
#pragma unroll
    for (int mt = 0; mt < 4; mt++)
#pragma unroll
        for (int nt = 0; nt < 4; nt++) {
            float2 v0 = make_float2(acc[mt][nt][0], acc[mt][nt][1]);
            float2 v1 = make_float2(acc[mt][nt][2], acc[mt][nt][3]);
            *reinterpret_cast<float2*>(&C[(size_t)(r0 + mt * 16)     * ldc + c0 + nt * 8]) = v0;
            *reinterpret_cast<float2*>(&C[(size_t)(r0 + mt * 16 + 8) * ldc + c0 + nt * 8]) = v1;
        }
}

// QKV GEMM with fused RoPE + fp16 hi/lo pack + [B,H,T,D] transpose epilogue.
__global__ __launch_bounds__(256, 2) void gemm_qkv(
    const __nv_bfloat16* __restrict__ Ah, const __nv_bfloat16* __restrict__ Al,
    const __nv_bfloat16* __restrict__ Bh, const __nv_bfloat16* __restrict__ Bl,
    const float2* __restrict__ tab,
    __half* __restrict__ Qh, __half* __restrict__ Ql,
    __half* __restrict__ Kh,
    __half* __restrict__ Vh, __half* __restrict__ Vl)
{
    extern __shared__ char smem[];
    uint32_t sb = smem_u32(smem);
    const int tid = threadIdx.x, wid = tid >> 5, lane = tid & 31;
    const int wm = wid >> 2, wn = wid & 3;
    const int bm = blockIdx.y * BM, bn = blockIdx.x * BN;

    float acc[4][4][4];
#pragma unroll
    for (int i = 0; i < 4; i++)
#pragma unroll
        for (int j = 0; j < 4; j++)
#pragma unroll
            for (int e = 0; e < 4; e++) acc[i][j][e] = 0.f;

    g_mainloop(sb, bm, bn, tid, lane, wm, wn, Ah, Al, Bh, Bl, acc);

    const int mat  = bn >> 11;                  // 0=Q,1=K,2=V
    const int head = (bn >> 7) & (NHEADS - 1);
    const float QSCL = 0.1275174456f;           // log2(e)/sqrt(128)

    const int r0 = bm + wm * 64 + (lane >> 2);
    const int c0 = (bn & 127) + wn * 32 + 2 * (lane & 3);
    const int b  = r0 >> 11;
    const size_t obase = ((size_t)(b * NHEADS + head)) * SEQ * DHEAD;

#pragma unroll
    for (int mt = 0; mt < 4; mt++) {
        const int tA = (r0 + mt * 16) & (SEQ - 1);
        const int tB = tA + 8;
#pragma unroll
        for (int nt = 0; nt < 4; nt++) {
            const int d = c0 + nt * 8;
            float x0 = acc[mt][nt][0], x1 = acc[mt][nt][1];
            float y0 = acc[mt][nt][2], y1 = acc[mt][nt][3];
            if (mat < 2) {
                float2 csA = tab[tA * 64 + (d >> 1)];
                float2 csB = tab[tB * 64 + (d >> 1)];
                float nx0 = x0 * csA.x - x1 * csA.y;
                float nx1 = x1 * csA.x + x0 * csA.y;
                float ny0 = y0 * csB.x - y1 * csB.y;
                float ny1 = y1 * csB.x + y0 * csB.y;
                x0 = nx0; x1 = nx1; y0 = ny0; y1 = ny1;
                if (mat == 0) { x0 *= QSCL; x1 *= QSCL; y0 *= QSCL; y1 *= QSCL; }
            }
            size_t dA = obase + (size_t)tA * DHEAD + d;
            size_t dB = obase + (size_t)tB * DHEAD + d;
            uint32_t hi, lo;
            if (mat == 0) {
                pack_hl(x0, x1, hi, lo);
                *reinterpret_cast<uint32_t*>(Qh + dA) = hi;
                *reinterpret_cast<uint32_t*>(Ql + dA) = lo;
                pack_hl(y0, y1, hi, lo);
                *reinterpret_cast<uint32_t*>(Qh + dB) = hi;
                *reinterpret_cast<uint32_t*>(Ql + dB) = lo;
            } else if (mat == 1) {
                __half2 k0 = __floats2half2_rn(x0, x1);
                __half2 k1 = __floats2half2_rn(y0, y1);
                *reinterpret_cast<__half2*>(Kh + dA) = k0;
                *reinterpret_cast<__half2*>(Kh + dB) = k1;
            } else {
                pack_hl(x0, x1, hi, lo);
                *reinterpret_cast<uint32_t*>(Vh + dA) = hi;
                *reinterpret_cast<uint32_t*>(Vl + dA) = lo;
                pack_hl(y0, y1, hi, lo);
                *reinterpret_cast<uint32_t*>(Vh + dB) = hi;
                *reinterpret_cast<uint32_t*>(Vl + dB) = lo;
            }
        }
    }
}

// ---------------------------------------------------------------------------
// Flash attention — round-6 configuration (best). TQ=128, TK=64, 8 warps,
// double-buffered KV, two barriers per k-tile.
// ---------------------------------------------------------------------------
#define AT_SROWB 272
#define SM_QH 0
#define SM_QL 34816
#define SM_K  69632
#define SM_V  104448
#define AT_SMEM 174080
#define KPART 17408
#define VBUFS 34816

static __device__ __forceinline__ void at_load_kv(
    uint32_t sb, int buf, int kt, size_t bh, int tid,
    const __half* __restrict__ Kh,
    const __half* __restrict__ Vh, const __half* __restrict__ Vl)
{
    const int k0 = kt * 64;
#pragma unroll
    for (int it = 0; it < 12; it++) {
        int idx = tid + it * 256;
        int part = idx >> 10;               // 0:Kh 1:Vh 2:Vl
        int rem = idx & 1023;
        int r = rem >> 4, ch = rem & 15;
        const __half* src = (part == 0) ? Kh : (part == 1) ? Vh : Vl;
        uint32_t dbase = (part == 0) ? (SM_K + buf * KPART)
                                     : (SM_V + buf * VBUFS + (part - 1) * KPART);
        cpasync16(sb + dbase + r * AT_SROWB + ch * 16,
                  src + ((size_t)(bh + k0 + r)) * DHEAD + ch * 8);
    }
    CP_COMMIT();
}

__global__ __launch_bounds__(256, 1) void attn_mma(
    const __half* __restrict__ Qh, const __half* __restrict__ Ql,
    const __half* __restrict__ Kh,
    const __half* __restrict__ Vh, const __half* __restrict__ Vl,
    __nv_bfloat16* __restrict__ Oh, __nv_bfloat16* __restrict__ Ol)
{
    extern __shared__ char smem[];
    uint32_t sb = smem_u32(smem);
    const int tid = threadIdx.x, lane = tid & 31, w = tid >> 5;
    const int qt = gridDim.x - 1 - blockIdx.x;
    const int h = blockIdx.y, b = blockIdx.z;
    const int q0 = qt * 128;
    const size_t bh = (size_t)(b * NHEADS + h) * SEQ;

    {
        const __half* gq0 = Qh + (bh + q0) * DHEAD;
        const __half* gq1 = Ql + (bh + q0) * DHEAD;
#pragma unroll
        for (int it = 0; it < 16; it++) {
            int idx = tid + it * 256;
            int part = idx >> 11, rem = idx & 2047;
            int r = rem >> 4, ch = rem & 15;
            const __half* src = part ? gq1 : gq0;
            cpasync16(sb + SM_QH + part * 34816 + r * AT_SROWB + ch * 16,
                      src + (size_t)r * DHEAD + ch * 8);
        }
        CP_COMMIT();
    }
    at_load_kv(sb, 0, 0, bh, tid, Kh, Vh, Vl);

    float m[2] = {-1e30f, -1e30f}, l[2] = {0.f, 0.f};
    float O[16][4];
#pragma unroll
    for (int i = 0; i < 16; i++)
#pragma unroll
        for (int e = 0; e < 4; e++) O[i][e] = 0.f;

    const uint32_t qha = sb + SM_QH + (w * 16 + (lane & 15)) * AT_SROWB + (((uint32_t)lane >> 4) << 3) * 2;
    const uint32_t qla = qha + 34816;
    const uint32_t koff = ((lane & 7) + ((lane & 16) >> 1)) * AT_SROWB + (((lane >> 3) & 1) << 3) * 2;
    const uint32_t voff = (lane & 15) * AT_SROWB + (((uint32_t)lane >> 4) << 3) * 2;
    const uint32_t ONES = 0x3C003C00u;

    const int nkt = 2 * qt + 2;
    for (int kt = 0; kt < nkt; kt++) {
        const int buf = kt & 1;
        __syncthreads();
        if (kt + 1 < nkt) {
            at_load_kv(sb, buf ^ 1, kt + 1, bh, tid, Kh, Vh, Vl);
            CP_WAIT1();
        } else {
            CP_WAIT0();
        }
        __syncthreads();

        // ---- S = Q K^T (2-term: Qh*Kh + Ql*Kh) ----
        float sacc[8][4];
#pragma unroll
        for (int nt = 0; nt < 8; nt++)
#pragma unroll
            for (int e = 0; e < 4; e++) sacc[nt][e] = 0.f;

        const uint32_t kbase = sb + SM_K + buf * KPART;
#pragma unroll
        for (int ks = 0; ks < 8; ks++) {
            uint32_t qh[4], ql[4];
            ldsm_x4(qh[0], qh[1], qh[2], qh[3], qha + ks * 32);
            ldsm_x4(ql[0], ql[1], ql[2], ql[3], qla + ks * 32);
#pragma unroll
            for (int np = 0; np < 4; np++) {
                uint32_t k0r, k1r, k2r, k3r;
                ldsm_x4(k0r, k1r, k2r, k3r,
                        kbase + koff + np * 16 * AT_SROWB + ks * 32);
                mma_f16(sacc[2*np],   qh, k0r, k1r);
                mma_f16(sacc[2*np],   ql, k0r, k1r);
                mma_f16(sacc[2*np+1], qh, k2r, k3r);
                mma_f16(sacc[2*np+1], ql, k2r, k3r);
            }
        }

        // ---- causal mask (diagonal tiles only) ----
        const int k0 = kt * 64;
        if (k0 + 63 > q0 + w * 16) {
            const int rA = q0 + w * 16 + (lane >> 2);
#pragma unroll
            for (int nt = 0; nt < 8; nt++) {
                int c = k0 + nt * 8 + 2 * (lane & 3);
                if (c     > rA)     sacc[nt][0] = -1e30f;
                if (c + 1 > rA)     sacc[nt][1] = -1e30f;
                if (c     > rA + 8) sacc[nt][2] = -1e30f;
                if (c + 1 > rA + 8) sacc[nt][3] = -1e30f;
            }
        }

        // ---- online softmax (log2 units) ----
        float mx0 = sacc[0][0], mx1 = sacc[0][2];
#pragma unroll
        for (int nt = 0; nt < 8; nt++) {
            mx0 = fmaxf(mx0, fmaxf(sacc[nt][0], sacc[nt][1]));
            mx1 = fmaxf(mx1, fmaxf(sacc[nt][2], sacc[nt][3]));
        }
        mx0 = fmaxf(mx0, __shfl_xor_sync(0xffffffffu, mx0, 1));
        mx0 = fmaxf(mx0, __shfl_xor_sync(0xffffffffu, mx0, 2));
        mx1 = fmaxf(mx1, __shfl_xor_sync(0xffffffffu, mx1, 1));
        mx1 = fmaxf(mx1, __shfl_xor_sync(0xffffffffu, mx1, 2));
        const float mn0 = fmaxf(m[0], mx0), mn1 = fmaxf(m[1], mx1);
        const float fac0 = exp2f(m[0] - mn0), fac1 = exp2f(m[1] - mn1);
        m[0] = mn0; m[1] = mn1;

        // ---- P = 2^(s - mn) as fp16 A-fragments ----
        uint32_t aPh[4][4];
#pragma unroll
        for (int ks = 0; ks < 4; ks++) {
            aPh[ks][0] = ex2_f16x2(sacc[2*ks][0]   - mn0, sacc[2*ks][1]   - mn0);
            aPh[ks][1] = ex2_f16x2(sacc[2*ks][2]   - mn1, sacc[2*ks][3]   - mn1);
            aPh[ks][2] = ex2_f16x2(sacc[2*ks+1][0] - mn0, sacc[2*ks+1][1] - mn0);
            aPh[ks][3] = ex2_f16x2(sacc[2*ks+1][2] - mn1, sacc[2*ks+1][3] - mn1);
        }

        // ---- rescale O; O += P V (2-term); l via ones-mma ----
#pragma unroll
        for (int i = 0; i < 16; i++) {
            O[i][0] *= fac0; O[i][1] *= fac0;
            O[i][2] *= fac1; O[i][3] *= fac1;
        }
        float Olsum[4] = {0.f, 0.f, 0.f, 0.f};
        const uint32_t vbase = sb + SM_V + buf * VBUFS;
#pragma unroll
        for (int ks = 0; ks < 4; ks++) {
            mma_f16(Olsum, aPh[ks], ONES, ONES);
#pragma unroll
            for (int dt = 0; dt < 8; dt++) {
                uint32_t va = vbase + voff + ks * 16 * AT_SROWB + dt * 32;
                uint32_t vh0, vh1, vh2, vh3, vl0, vl1, vl2, vl3;
                ldsm_x4t(vh0, vh1, vh2, vh3, va);
                ldsm_x4t(vl0, vl1, vl2, vl3, va + KPART);
                mma_f16(O[2*dt],   aPh[ks], vh0, vh1);
                mma_f16(O[2*dt+1], aPh[ks], vh2, vh3);
                mma_f16(O[2*dt],   aPh[ks], vl0, vl1);
                mma_f16(O[2*dt+1], aPh[ks], vl2, vl3);
            }
        }
        l[0] = l[0] * fac0 + Olsum[0];
        l[1] = l[1] * fac1 + Olsum[2];
    }

    // ---- normalize & write bf16 hi/lo ----
    const float inv0 = 1.f / l[0], inv1 = 1.f / l[1];
    const int rowA = q0 + w * 16 + (lane >> 2);
    const size_t baseA = ((size_t)b * SEQ + rowA) * DMODEL + h * DHEAD;
    const size_t baseB = baseA + (size_t)8 * DMODEL;
#pragma unroll
    for (int nt = 0; nt < 16; nt++) {
        int d = nt * 8 + 2 * (lane & 3);
        float o0 = O[nt][0] * inv0, o1 = O[nt][1] * inv0;
        float o2 = O[nt][2] * inv1, o3 = O[nt][3] * inv1;
        __nv_bfloat162 h0, l0h, h2, l2h;
        h0.x = __float2bfloat16(o0); h0.y = __float2bfloat16(o1);
        l0h.x = __float2bfloat16(o0 - __bfloat162float(h0.x));
        l0h.y = __float2bfloat16(o1 - __bfloat162float(h0.y));
        h2.x = __float2bfloat16(o2); h2.y = __float2bfloat16(o3);
        l2h.x = __float2bfloat16(o2 - __bfloat162float(h2.x));
        l2h.y = __float2bfloat16(o3 - __bfloat162float(h2.y));
        *reinterpret_cast<__nv_bfloat162*>(Oh + baseA + d) = h0;
        *reinterpret_cast<__nv_bfloat162*>(Ol + baseA + d) = l0h;
        *reinterpret_cast<__nv_bfloat162*>(Oh + baseB + d) = h2;
        *reinterpret_cast<__nv_bfloat162*>(Ol + baseB + d) = l2h;
    }
}

// ---------------------------------------------------------------------------
extern "C" void kernel_launch(void* const* d_in, const int* in_sizes, int n_in,
                              void* d_out, int out_size)
{
    const float* x    = (const float*)d_in[0];
    const float* Wqkv = (const float*)d_in[1];
    const float* WO   = (const float*)d_in[2];
    float* out = (float*)d_out;

    float2* rope;
    cudaGetSymbolAddress((void**)&rope, g_rope);
    __nv_bfloat16 *xh, *xl, *wqh, *wql, *ah, *al, *wh, *wl;
    cudaGetSymbolAddress((void**)&xh, g_xh);   cudaGetSymbolAddress((void**)&xl, g_xl);
    cudaGetSymbolAddress((void**)&wqh, g_wqh); cudaGetSymbolAddress((void**)&wql, g_wql);
    cudaGetSymbolAddress((void**)&ah, g_ah);   cudaGetSymbolAddress((void**)&al, g_al);
    cudaGetSymbolAddress((void**)&wh, g_wh);   cudaGetSymbolAddress((void**)&wl, g_wl);
    __half *qh16, *ql16, *kh16, *vh16, *vl16;
    cudaGetSymbolAddress((void**)&qh16, g_qh16); cudaGetSymbolAddress((void**)&ql16, g_ql16);
    cudaGetSymbolAddress((void**)&kh16, g_kh16);
    cudaGetSymbolAddress((void**)&vh16, g_vh16); cudaGetSymbolAddress((void**)&vl16, g_vl16);

    cudaFuncSetAttribute(gemm_mma, cudaFuncAttributeMaxDynamicSharedMemorySize, GSMEM);
    cudaFuncSetAttribute(gemm_qkv, cudaFuncAttributeMaxDynamicSharedMemorySize, GSMEM);
    cudaFuncSetAttribute(attn_mma, cudaFuncAttributeMaxDynamicSharedMemorySize, AT_SMEM);

    rope_table_kernel<<<(SEQ * 64) / 256, 256>>>(rope);
    { int n4 = (MROWS * KDIM) / 4;
      split_kernel<<<(n4 + 255) / 256, 256>>>((const float4*)x, (uint2*)xh, (uint2*)xl, n4); }
    { int n4 = (QKVDIM * KDIM) / 4;
      split_kernel<<<(n4 + 255) / 256, 256>>>((const float4*)Wqkv, (uint2*)wqh, (uint2*)wql, n4); }
    { int n4 = (DMODEL * KDIM) / 4;
      split_kernel<<<(n4 + 255) / 256, 256>>>((const float4*)WO, (uint2*)wh, (uint2*)wl, n4); }

    // 1) QKV GEMM with fused RoPE + fp16 pack + [B,H,T,D] transpose
    {
        dim3 grid(QKVDIM / BN, MROWS / BM);
        gemm_qkv<<<grid, 256, GSMEM>>>(xh, xl, wqh, wql, rope,
                                       qh16, ql16, kh16, vh16, vl16);
    }

    // 2) flash attention -> bf16 hi/lo (ah, al)
    {
        dim3 grid(SEQ / 128, NHEADS, BATCH);
        attn_mma<<<grid, 256, AT_SMEM>>>(qh16, ql16, kh16, vh16, vl16, ah, al);
    }

    // 3) out = att @ WO^T
    {
        dim3 grid(DMODEL / BN, MROWS / BM);
        gemm_mma<<<grid, 256, GSMEM>>>(ah, al, wh, wl, out, DMODEL);
    }
}

// round 10
// speedup vs baseline: 1.6129x; 1.0476x over previous
#include <cuda_runtime.h>
#include <cuda_bf16.h>
#include <cuda_fp16.h>
#include <math.h>
#include <stdint.h>

// Problem constants
#define BATCH   2
#define SEQ     2048
#define DMODEL  2048
#define NHEADS  16
#define DHEAD   128
#define MROWS   (BATCH*SEQ)          // 4096
#define QKVDIM  (3*DMODEL)           // 6144
#define KDIM    2048

// Scratch (__device__ globals; allocation-free rule)
__device__ float2 g_rope[(size_t)SEQ * 64];
__device__ __nv_bfloat16 g_xh[(size_t)MROWS * KDIM],   g_xl[(size_t)MROWS * KDIM];
__device__ __nv_bfloat16 g_wqh[(size_t)QKVDIM * KDIM], g_wql[(size_t)QKVDIM * KDIM];
__device__ __nv_bfloat16 g_ah[(size_t)MROWS * KDIM],   g_al[(size_t)MROWS * KDIM];
__device__ __nv_bfloat16 g_wh[(size_t)DMODEL * KDIM],  g_wl[(size_t)DMODEL * KDIM];
// fp16 attention operands, [B][H][T][D]
#define NATT ((size_t)BATCH * NHEADS * SEQ * DHEAD)
__device__ __half g_qh16[NATT], g_ql16[NATT];
__device__ __half g_kh16[NATT];
__device__ __half g_vh16[NATT];

// ---------------------------------------------------------------------------
// PTX helpers
// ---------------------------------------------------------------------------
static __device__ __forceinline__ uint32_t smem_u32(const void* p) {
    uint32_t a;
    asm("{ .reg .u64 t; cvta.to.shared.u64 t, %1; cvt.u32.u64 %0, t; }" : "=r"(a) : "l"(p));
    return a;
}
static __device__ __forceinline__ void cpasync16(uint32_t dst, const void* src) {
    asm volatile("cp.async.cg.shared.global [%0], [%1], 16;\n" :: "r"(dst), "l"(src));
}
#define CP_COMMIT() asm volatile("cp.async.commit_group;\n" ::: "memory")
#define CP_WAIT0()  asm volatile("cp.async.wait_group 0;\n" ::: "memory")
#define CP_WAIT1()  asm volatile("cp.async.wait_group 1;\n" ::: "memory")

static __device__ __forceinline__ void ldsm_x4(uint32_t& r0, uint32_t& r1,
                                               uint32_t& r2, uint32_t& r3, uint32_t a) {
    asm volatile("ldmatrix.sync.aligned.m8n8.x4.shared.b16 {%0,%1,%2,%3}, [%4];"
                 : "=r"(r0), "=r"(r1), "=r"(r2), "=r"(r3) : "r"(a));
}
static __device__ __forceinline__ void ldsm_x4t(uint32_t& r0, uint32_t& r1,
                                                uint32_t& r2, uint32_t& r3, uint32_t a) {
    asm volatile("ldmatrix.sync.aligned.m8n8.x4.trans.shared.b16 {%0,%1,%2,%3}, [%4];"
                 : "=r"(r0), "=r"(r1), "=r"(r2), "=r"(r3) : "r"(a));
}
static __device__ __forceinline__ void mma_bf16(float* c, const uint32_t* a,
                                                uint32_t b0, uint32_t b1) {
    asm volatile(
        "mma.sync.aligned.m16n8k16.row.col.f32.bf16.bf16.f32 "
        "{%0,%1,%2,%3}, {%4,%5,%6,%7}, {%8,%9}, {%0,%1,%2,%3};"
        : "+f"(c[0]), "+f"(c[1]), "+f"(c[2]), "+f"(c[3])
        : "r"(a[0]), "r"(a[1]), "r"(a[2]), "r"(a[3]), "r"(b0), "r"(b1));
}
static __device__ __forceinline__ void mma_f16(float* c, const uint32_t* a,
                                               uint32_t b0, uint32_t b1) {
    asm volatile(
        "mma.sync.aligned.m16n8k16.row.col.f32.f16.f16.f32 "
        "{%0,%1,%2,%3}, {%4,%5,%6,%7}, {%8,%9}, {%0,%1,%2,%3};"
        : "+f"(c[0]), "+f"(c[1]), "+f"(c[2]), "+f"(c[3])
        : "r"(a[0]), "r"(a[1]), "r"(a[2]), "r"(a[3]), "r"(b0), "r"(b1));
}
static __device__ __forceinline__ void pack_hl(float f0, float f1, uint32_t& hi, uint32_t& lo) {
    __half2 h = __floats2half2_rn(f0, f1);
    float2 fb = __half22float2(h);
    __half2 l2 = __floats2half2_rn(f0 - fb.x, f1 - fb.y);
    hi = *reinterpret_cast<uint32_t*>(&h);
    lo = *reinterpret_cast<uint32_t*>(&l2);
}
static __device__ __forceinline__ uint32_t ex2_f16x2(float a, float b) {
    uint32_t d;
    asm("{ .reg .b32 t;\n cvt.rn.f16x2.f32 t, %2, %1;\n ex2.approx.f16x2 %0, t;\n}"
        : "=r"(d) : "f"(a), "f"(b));
    return d;
}

// ---------------------------------------------------------------------------
// fp32 -> bf16 hi/lo split, vectorized x4
// ---------------------------------------------------------------------------
__global__ __launch_bounds__(256) void split_kernel(
    const float4* __restrict__ s, uint2* __restrict__ hi,
    uint2* __restrict__ lo, int n4)
{
    int i = blockIdx.x * 256 + threadIdx.x;
    if (i >= n4) return;
    float4 v = s[i];
    __nv_bfloat162 h01, h23, l01, l23;
    h01.x = __float2bfloat16(v.x); h01.y = __float2bfloat16(v.y);
    h23.x = __float2bfloat16(v.z); h23.y = __float2bfloat16(v.w);
    l01.x = __float2bfloat16(v.x - __bfloat162float(h01.x));
    l01.y = __float2bfloat16(v.y - __bfloat162float(h01.y));
    l23.x = __float2bfloat16(v.z - __bfloat162float(h23.x));
    l23.y = __float2bfloat16(v.w - __bfloat162float(h23.y));
    uint2 hv, lv;
    hv.x = *reinterpret_cast<uint32_t*>(&h01); hv.y = *reinterpret_cast<uint32_t*>(&h23);
    lv.x = *reinterpret_cast<uint32_t*>(&l01); lv.y = *reinterpret_cast<uint32_t*>(&l23);
    hi[i] = hv;
    lo[i] = lv;
}

// ---------------------------------------------------------------------------
// RoPE cos/sin table
// ---------------------------------------------------------------------------
__global__ __launch_bounds__(256) void rope_table_kernel(float2* __restrict__ tab)
{
    int idx = blockIdx.x * 256 + threadIdx.x;
    int i = idx & 63, t = idx >> 6;
    double freq = exp(-9.210340371976184 * (double)(2 * i) / 128.0);
    double sd, cd;
    sincos((double)t * freq, &sd, &cd);
    tab[idx] = make_float2((float)cd, (float)sd);
}

// ---------------------------------------------------------------------------
// GEMM mainloop (NT, bf16 hi/lo 3-term) — round-6 configuration (best).
// BM=BN=128, BK=32, 256 threads, 8 warps (2m x 4n), warp tile 64x32, occ 2.
// ---------------------------------------------------------------------------
#define BM 128
#define BN 128
#define BK 32
#define SROW 40
#define PART_BYTES (128 * SROW * 2)
#define STG_BYTES  (4 * PART_BYTES)
#define AH_OFF 0
#define AL_OFF PART_BYTES
#define BH_OFF (2 * PART_BYTES)
#define BL_OFF (3 * PART_BYTES)
#define GSMEM (2 * STG_BYTES)

static __device__ __forceinline__ void g_load_stage(
    uint32_t sb, int buf, int s, int bm, int bn, int tid,
    const __nv_bfloat16* __restrict__ Ah, const __nv_bfloat16* __restrict__ Al,
    const __nv_bfloat16* __restrict__ Bh, const __nv_bfloat16* __restrict__ Bl)
{
    uint32_t base = sb + buf * STG_BYTES;
    const int k0 = s * BK;
#pragma unroll
    for (int it = 0; it < 2; it++) {
        int idx = tid + it * 256;
        int r = idx >> 2, ch = idx & 3;
        uint32_t so = r * (SROW * 2) + ch * 16;
        size_t ga = (size_t)(bm + r) * KDIM + k0 + ch * 8;
        size_t gb = (size_t)(bn + r) * KDIM + k0 + ch * 8;
        cpasync16(base + AH_OFF + so, Ah + ga);
        cpasync16(base + AL_OFF + so, Al + ga);
        cpasync16(base + BH_OFF + so, Bh + gb);
        cpasync16(base + BL_OFF + so, Bl + gb);
    }
    CP_COMMIT();
}

static __device__ __forceinline__ void g_mainloop(
    uint32_t sb, int bm, int bn, int tid, int lane, int wm, int wn,
    const __nv_bfloat16* __restrict__ Ah, const __nv_bfloat16* __restrict__ Al,
    const __nv_bfloat16* __restrict__ Bh, const __nv_bfloat16* __restrict__ Bl,
    float acc[4][4][4])
{
    const uint32_t aRow = wm * 64 + (lane & 15);
    const uint32_t aCol = (lane >> 4) << 3;
    const uint32_t bOff = (wn * 32 + (lane & 7) + ((lane & 16) >> 1)) * (SROW * 2)
                        + (((lane >> 3) & 1) << 3) * 2;

    g_load_stage(sb, 0, 0, bm, bn, tid, Ah, Al, Bh, Bl);

    const int NS = KDIM / BK;
    for (int s = 0; s < NS; s++) {
        const int buf = s & 1;
        if (s + 1 < NS) {
            g_load_stage(sb, buf ^ 1, s + 1, bm, bn, tid, Ah, Al, Bh, Bl);
            CP_WAIT1();
        } else {
            CP_WAIT0();
        }
        __syncthreads();

        uint32_t base = sb + buf * STG_BYTES;
#pragma unroll
        for (int kk = 0; kk < BK; kk += 16) {
            uint32_t af[4][4], bh[4][2], bl[4][2];
#pragma unroll
            for (int mt = 0; mt < 4; mt++)
                ldsm_x4(af[mt][0], af[mt][1], af[mt][2], af[mt][3],
                        base + AH_OFF + (aRow + mt * 16) * (SROW * 2) + (aCol + kk) * 2);
#pragma unroll
            for (int np = 0; np < 2; np++) {
                ldsm_x4(bh[2*np][0], bh[2*np][1], bh[2*np+1][0], bh[2*np+1][1],
                        base + BH_OFF + bOff + np * 16 * (SROW * 2) + kk * 2);
                ldsm_x4(bl[2*np][0], bl[2*np][1], bl[2*np+1][0], bl[2*np+1][1],
                        base + BL_OFF + bOff + np * 16 * (SROW * 2) + kk * 2);
            }
            // Ah x Bh
#pragma unroll
            for (int mt = 0; mt < 4; mt++)
#pragma unroll
                for (int nt = 0; nt < 4; nt++)
                    mma_bf16(acc[mt][nt], af[mt], bh[nt][0], bh[nt][1]);
            // Ah x Bl
#pragma unroll
            for (int mt = 0; mt < 4; mt++)
#pragma unroll
                for (int nt = 0; nt < 4; nt++)
                    mma_bf16(acc[mt][nt], af[mt], bl[nt][0], bl[nt][1]);
            // Al x Bh
#pragma unroll
            for (int mt = 0; mt < 4; mt++)
                ldsm_x4(af[mt][0], af[mt][1], af[mt][2], af[mt][3],
                        base + AL_OFF + (aRow + mt * 16) * (SROW * 2) + (aCol + kk) * 2);
#pragma unroll
            for (int mt = 0; mt < 4; mt++)
#pragma unroll
                for (int nt = 0; nt < 4; nt++)
                    mma_bf16(acc[mt][nt], af[mt], bh[nt][0], bh[nt][1]);
        }
        __syncthreads();
    }
}

// Plain fp32-output GEMM (WO projection)
__global__ __launch_bounds__(256, 2) void gemm_mma(
    const __nv_bfloat16* __restrict__ Ah, const __nv_bfloat16* __restrict__ Al,
    const __nv_bfloat16* __restrict__ Bh, const __nv_bfloat16* __restrict__ Bl,
    float* __restrict__ C, int ldc)
{
    extern __shared__ char smem[];
    uint32_t sb = smem_u32(smem);
    const int tid = threadIdx.x, wid = tid >> 5, lane = tid & 31;
    const int wm = wid >> 2, wn = wid & 3;
    const int bm = blockIdx.y * BM, bn = blockIdx.x * BN;

    float acc[4][4][4];
#pragma unroll
    for (int i = 0; i < 4; i++)
#pragma unroll
        for (int j = 0; j < 4; j++)
#pragma unroll
            for (int e = 0; e < 4; e++) acc[i][j][e] = 0.f;

    g_mainloop(sb, bm, bn, tid, lane, wm, wn, Ah, Al, Bh, Bl, acc);

    const int r0 = bm + wm * 64 + (lane >> 2);
    const int c0 = bn + wn * 32 + 2 * (lane & 3);
#pragma unroll
    for (int mt = 0; mt < 4; mt++)
#pragma unroll
        for (int nt = 0; nt < 4; nt++) {
            float2 v0 = make_float2(acc[mt][nt][0], acc[mt][nt][1]);
            float2 v1 = make_float2(acc[mt][nt][2], acc[mt][nt][3]);
            *reinterpret_cast<float2*>(&C[(size_t)(r0 + mt * 16)     * ldc + c0 + nt * 8]) = v0;
            *reinterpret_cast<float2*>(&C[(size_t)(r0 + mt * 16 + 8) * ldc + c0 + nt * 8]) = v1;
        }
}

// QKV GEMM with fused RoPE + fp16 pack + [B,H,T,D] transpose epilogue.
// Q: fp16 hi/lo; K: fp16; V: fp16 (V-lo dropped — PV error ~1.2e-4 rms, within budget).
__global__ __launch_bounds__(256, 2) void gemm_qkv(
    const __nv_bfloat16* __restrict__ Ah, const __nv_bfloat16* __restrict__ Al,
    const __nv_bfloat16* __restrict__ Bh, const __nv_bfloat16* __restrict__ Bl,
    const float2* __restrict__ tab,
    __half* __restrict__ Qh, __half* __restrict__ Ql,
    __half* __restrict__ Kh, __half* __restrict__ Vh)
{
    extern __shared__ char smem[];
    uint32_t sb = smem_u32(smem);
    const int tid = threadIdx.x, wid = tid >> 5, lane = tid & 31;
    const int wm = wid >> 2, wn = wid & 3;
    const int bm = blockIdx.y * BM, bn = blockIdx.x * BN;

    float acc[4][4][4];
#pragma unroll
    for (int i = 0; i < 4; i++)
#pragma unroll
        for (int j = 0; j < 4; j++)
#pragma unroll
            for (int e = 0; e < 4; e++) acc[i][j][e] = 0.f;

    g_mainloop(sb, bm, bn, tid, lane, wm, wn, Ah, Al, Bh, Bl, acc);

    const int mat  = bn >> 11;                  // 0=Q,1=K,2=V
    const int head = (bn >> 7) & (NHEADS - 1);
    const float QSCL = 0.1275174456f;           // log2(e)/sqrt(128)

    const int r0 = bm + wm * 64 + (lane >> 2);
    const int c0 = (bn & 127) + wn * 32 + 2 * (lane & 3);
    const int b  = r0 >> 11;
    const size_t obase = ((size_t)(b * NHEADS + head)) * SEQ * DHEAD;

#pragma unroll
    for (int mt = 0; mt < 4; mt++) {
        const int tA = (r0 + mt * 16) & (SEQ - 1);
        const int tB = tA + 8;
#pragma unroll
        for (int nt = 0; nt < 4; nt++) {
            const int d = c0 + nt * 8;
            float x0 = acc[mt][nt][0], x1 = acc[mt][nt][1];
            float y0 = acc[mt][nt][2], y1 = acc[mt][nt][3];
            if (mat < 2) {
                float2 csA = tab[tA * 64 + (d >> 1)];
                float2 csB = tab[tB * 64 + (d >> 1)];
                float nx0 = x0 * csA.x - x1 * csA.y;
                float nx1 = x1 * csA.x + x0 * csA.y;
                float ny0 = y0 * csB.x - y1 * csB.y;
                float ny1 = y1 * csB.x + y0 * csB.y;
                x0 = nx0; x1 = nx1; y0 = ny0; y1 = ny1;
                if (mat == 0) { x0 *= QSCL; x1 *= QSCL; y0 *= QSCL; y1 *= QSCL; }
            }
            size_t dA = obase + (size_t)tA * DHEAD + d;
            size_t dB = obase + (size_t)tB * DHEAD + d;
            if (mat == 0) {
                uint32_t hi, lo;
                pack_hl(x0, x1, hi, lo);
                *reinterpret_cast<uint32_t*>(Qh + dA) = hi;
                *reinterpret_cast<uint32_t*>(Ql + dA) = lo;
                pack_hl(y0, y1, hi, lo);
                *reinterpret_cast<uint32_t*>(Qh + dB) = hi;
                *reinterpret_cast<uint32_t*>(Ql + dB) = lo;
            } else {
                __half* D = (mat == 1) ? Kh : Vh;
                __half2 v0 = __floats2half2_rn(x0, x1);
                __half2 v1 = __floats2half2_rn(y0, y1);
                *reinterpret_cast<__half2*>(D + dA) = v0;
                *reinterpret_cast<__half2*>(D + dB) = v1;
            }
        }
    }
}

// ---------------------------------------------------------------------------
// Flash attention — round-6 pipeline shape; Q fragments hoisted to registers;
// V fp16 single-term. TQ=128, TK=64, 8 warps, double-buffered KV.
// ---------------------------------------------------------------------------
#define AT_SROWB 272
#define SM_QH 0
#define SM_QL 34816
#define SM_K  69632
#define SM_V  104448
#define KPART 17408
#define AT_SMEM 139264

static __device__ __forceinline__ void at_load_kv(
    uint32_t sb, int buf, int kt, size_t bh, int tid,
    const __half* __restrict__ Kh, const __half* __restrict__ Vh)
{
    const int k0 = kt * 64;
#pragma unroll
    for (int it = 0; it < 8; it++) {
        int idx = tid + it * 256;           // 0..2047
        int part = idx >> 10;               // 0:Kh 1:Vh
        int rem = idx & 1023;
        int r = rem >> 4, ch = rem & 15;
        const __half* src = (part == 0) ? Kh : Vh;
        uint32_t dbase = ((part == 0) ? SM_K : SM_V) + buf * KPART;
        cpasync16(sb + dbase + r * AT_SROWB + ch * 16,
                  src + ((size_t)(bh + k0 + r)) * DHEAD + ch * 8);
    }
    CP_COMMIT();
}

__global__ __launch_bounds__(256, 1) void attn_mma(
    const __half* __restrict__ Qh, const __half* __restrict__ Ql,
    const __half* __restrict__ Kh, const __half* __restrict__ Vh,
    __nv_bfloat16* __restrict__ Oh, __nv_bfloat16* __restrict__ Ol)
{
    extern __shared__ char smem[];
    uint32_t sb = smem_u32(smem);
    const int tid = threadIdx.x, lane = tid & 31, w = tid >> 5;
    const int qt = gridDim.x - 1 - blockIdx.x;
    const int h = blockIdx.y, b = blockIdx.z;
    const int q0 = qt * 128;
    const size_t bh = (size_t)(b * NHEADS + h) * SEQ;

    // Q load (group A)
    {
        const __half* gq0 = Qh + (bh + q0) * DHEAD;
        const __half* gq1 = Ql + (bh + q0) * DHEAD;
#pragma unroll
        for (int it = 0; it < 16; it++) {
            int idx = tid + it * 256;
            int part = idx >> 11, rem = idx & 2047;
            int r = rem >> 4, ch = rem & 15;
            const __half* src = part ? gq1 : gq0;
            cpasync16(sb + SM_QH + part * 34816 + r * AT_SROWB + ch * 16,
                      src + (size_t)r * DHEAD + ch * 8);
        }
        CP_COMMIT();
    }
    at_load_kv(sb, 0, 0, bh, tid, Kh, Vh);   // group B

    // Wait for Q (group A) to land, then hoist Q fragments into registers.
    const uint32_t qha = sb + SM_QH + (w * 16 + (lane & 15)) * AT_SROWB + (((uint32_t)lane >> 4) << 3) * 2;
    const uint32_t qla = qha + 34816;
    uint32_t qhf[8][4], qlf[8][4];
    CP_WAIT1();                 // group A complete (B may be in flight)
    __syncthreads();
#pragma unroll
    for (int ks = 0; ks < 8; ks++) {
        ldsm_x4(qhf[ks][0], qhf[ks][1], qhf[ks][2], qhf[ks][3], qha + ks * 32);
        ldsm_x4(qlf[ks][0], qlf[ks][1], qlf[ks][2], qlf[ks][3], qla + ks * 32);
    }

    float m[2] = {-1e30f, -1e30f}, l[2] = {0.f, 0.f};
    float O[16][4];
#pragma unroll
    for (int i = 0; i < 16; i++)
#pragma unroll
        for (int e = 0; e < 4; e++) O[i][e] = 0.f;

    const uint32_t koff = ((lane & 7) + ((lane & 16) >> 1)) * AT_SROWB + (((lane >> 3) & 1) << 3) * 2;
    const uint32_t voff = (lane & 15) * AT_SROWB + (((uint32_t)lane >> 4) << 3) * 2;
    const uint32_t ONES = 0x3C003C00u;

    const int nkt = 2 * qt + 2;
    for (int kt = 0; kt < nkt; kt++) {
        const int buf = kt & 1;
        __syncthreads();
        if (kt + 1 < nkt) {
            at_load_kv(sb, buf ^ 1, kt + 1, bh, tid, Kh, Vh);
            CP_WAIT1();
        } else {
            CP_WAIT0();
        }
        __syncthreads();

        // ---- S = Q K^T (2-term: Qh*Kh + Ql*Kh), Q from registers ----
        float sacc[8][4];
#pragma unroll
        for (int nt = 0; nt < 8; nt++)
#pragma unroll
            for (int e = 0; e < 4; e++) sacc[nt][e] = 0.f;

        const uint32_t kbase = sb + SM_K + buf * KPART;
#pragma unroll
        for (int ks = 0; ks < 8; ks++) {
#pragma unroll
            for (int np = 0; np < 4; np++) {
                uint32_t k0r, k1r, k2r, k3r;
                ldsm_x4(k0r, k1r, k2r, k3r,
                        kbase + koff + np * 16 * AT_SROWB + ks * 32);
                mma_f16(sacc[2*np],   qhf[ks], k0r, k1r);
                mma_f16(sacc[2*np],   qlf[ks], k0r, k1r);
                mma_f16(sacc[2*np+1], qhf[ks], k2r, k3r);
                mma_f16(sacc[2*np+1], qlf[ks], k2r, k3r);
            }
        }

        // ---- causal mask (diagonal tiles only) ----
        const int k0 = kt * 64;
        if (k0 + 63 > q0 + w * 16) {
            const int rA = q0 + w * 16 + (lane >> 2);
#pragma unroll
            for (int nt = 0; nt < 8; nt++) {
                int c = k0 + nt * 8 + 2 * (lane & 3);
                if (c     > rA)     sacc[nt][0] = -1e30f;
                if (c + 1 > rA)     sacc[nt][1] = -1e30f;
                if (c     > rA + 8) sacc[nt][2] = -1e30f;
                if (c + 1 > rA + 8) sacc[nt][3] = -1e30f;
            }
        }

        // ---- online softmax (log2 units) ----
        float mx0 = sacc[0][0], mx1 = sacc[0][2];
#pragma unroll
        for (int nt = 0; nt < 8; nt++) {
            mx0 = fmaxf(mx0, fmaxf(sacc[nt][0], sacc[nt][1]));
            mx1 = fmaxf(mx1, fmaxf(sacc[nt][2], sacc[nt][3]));
        }
        mx0 = fmaxf(mx0, __shfl_xor_sync(0xffffffffu, mx0, 1));
        mx0 = fmaxf(mx0, __shfl_xor_sync(0xffffffffu, mx0, 2));
        mx1 = fmaxf(mx1, __shfl_xor_sync(0xffffffffu, mx1, 1));
        mx1 = fmaxf(mx1, __shfl_xor_sync(0xffffffffu, mx1, 2));
        const float mn0 = fmaxf(m[0], mx0), mn1 = fmaxf(m[1], mx1);
        const float fac0 = exp2f(m[0] - mn0), fac1 = exp2f(m[1] - mn1);
        m[0] = mn0; m[1] = mn1;

        // ---- P = 2^(s - mn) as fp16 A-fragments ----
        uint32_t aPh[4][4];
#pragma unroll
        for (int ks = 0; ks < 4; ks++) {
            aPh[ks][0] = ex2_f16x2(sacc[2*ks][0]   - mn0, sacc[2*ks][1]   - mn0);
            aPh[ks][1] = ex2_f16x2(sacc[2*ks][2]   - mn1, sacc[2*ks][3]   - mn1);
            aPh[ks][2] = ex2_f16x2(sacc[2*ks+1][0] - mn0, sacc[2*ks+1][1] - mn0);
            aPh[ks][3] = ex2_f16x2(sacc[2*ks+1][2] - mn1, sacc[2*ks+1][3] - mn1);
        }

        // ---- rescale O; O += P Vh (1-term); l via ones-mma ----
#pragma unroll
        for (int i = 0; i < 16; i++) {
            O[i][0] *= fac0; O[i][1] *= fac0;
            O[i][2] *= fac1; O[i][3] *= fac1;
        }
        float Olsum[4] = {0.f, 0.f, 0.f, 0.f};
        const uint32_t vbase = sb + SM_V + buf * KPART;
#pragma unroll
        for (int ks = 0; ks < 4; ks++) {
            mma_f16(Olsum, aPh[ks], ONES, ONES);
#pragma unroll
            for (int dt = 0; dt < 8; dt++) {
                uint32_t va = vbase + voff + ks * 16 * AT_SROWB + dt * 32;
                uint32_t vh0, vh1, vh2, vh3;
                ldsm_x4t(vh0, vh1, vh2, vh3, va);
                mma_f16(O[2*dt],   aPh[ks], vh0, vh1);
                mma_f16(O[2*dt+1], aPh[ks], vh2, vh3);
            }
        }
        l[0] = l[0] * fac0 + Olsum[0];
        l[1] = l[1] * fac1 + Olsum[2];
    }

    // ---- normalize & write bf16 hi/lo ----
    const float inv0 = 1.f / l[0], inv1 = 1.f / l[1];
    const int rowA = q0 + w * 16 + (lane >> 2);
    const size_t baseA = ((size_t)b * SEQ + rowA) * DMODEL + h * DHEAD;
    const size_t baseB = baseA + (size_t)8 * DMODEL;
#pragma unroll
    for (int nt = 0; nt < 16; nt++) {
        int d = nt * 8 + 2 * (lane & 3);
        float o0 = O[nt][0] * inv0, o1 = O[nt][1] * inv0;
        float o2 = O[nt][2] * inv1, o3 = O[nt][3] * inv1;
        __nv_bfloat162 h0, l0h, h2, l2h;
        h0.x = __float2bfloat16(o0); h0.y = __float2bfloat16(o1);
        l0h.x = __float2bfloat16(o0 - __bfloat162float(h0.x));
        l0h.y = __float2bfloat16(o1 - __bfloat162float(h0.y));
        h2.x = __float2bfloat16(o2); h2.y = __float2bfloat16(o3);
        l2h.x = __float2bfloat16(o2 - __bfloat162float(h2.x));
        l2h.y = __float2bfloat16(o3 - __bfloat162float(h2.y));
        *reinterpret_cast<__nv_bfloat162*>(Oh + baseA + d) = h0;
        *reinterpret_cast<__nv_bfloat162*>(Ol + baseA + d) = l0h;
        *reinterpret_cast<__nv_bfloat162*>(Oh + baseB + d) = h2;
        *reinterpret_cast<__nv_bfloat162*>(Ol + baseB + d) = l2h;
    }
}

// ---------------------------------------------------------------------------
extern "C" void kernel_launch(void* const* d_in, const int* in_sizes, int n_in,
                              void* d_out, int out_size)
{
    const float* x    = (const float*)d_in[0];
    const float* Wqkv = (const float*)d_in[1];
    const float* WO   = (const float*)d_in[2];
    float* out = (float*)d_out;

    float2* rope;
    cudaGetSymbolAddress((void**)&rope, g_rope);
    __nv_bfloat16 *xh, *xl, *wqh, *wql, *ah, *al, *wh, *wl;
    cudaGetSymbolAddress((void**)&xh, g_xh);   cudaGetSymbolAddress((void**)&xl, g_xl);
    cudaGetSymbolAddress((void**)&wqh, g_wqh); cudaGetSymbolAddress((void**)&wql, g_wql);
    cudaGetSymbolAddress((void**)&ah, g_ah);   cudaGetSymbolAddress((void**)&al, g_al);
    cudaGetSymbolAddress((void**)&wh, g_wh);   cudaGetSymbolAddress((void**)&wl, g_wl);
    __half *qh16, *ql16, *kh16, *vh16;
    cudaGetSymbolAddress((void**)&qh16, g_qh16); cudaGetSymbolAddress((void**)&ql16, g_ql16);
    cudaGetSymbolAddress((void**)&kh16, g_kh16); cudaGetSymbolAddress((void**)&vh16, g_vh16);

    cudaFuncSetAttribute(gemm_mma, cudaFuncAttributeMaxDynamicSharedMemorySize, GSMEM);
    cudaFuncSetAttribute(gemm_qkv, cudaFuncAttributeMaxDynamicSharedMemorySize, GSMEM);
    cudaFuncSetAttribute(attn_mma, cudaFuncAttributeMaxDynamicSharedMemorySize, AT_SMEM);

    rope_table_kernel<<<(SEQ * 64) / 256, 256>>>(rope);
    { int n4 = (MROWS * KDIM) / 4;
      split_kernel<<<(n4 + 255) / 256, 256>>>((const float4*)x, (uint2*)xh, (uint2*)xl, n4); }
    { int n4 = (QKVDIM * KDIM) / 4;
      split_kernel<<<(n4 + 255) / 256, 256>>>((const float4*)Wqkv, (uint2*)wqh, (uint2*)wql, n4); }
    { int n4 = (DMODEL * KDIM) / 4;
      split_kernel<<<(n4 + 255) / 256, 256>>>((const float4*)WO, (uint2*)wh, (uint2*)wl, n4); }

    // 1) QKV GEMM with fused RoPE + fp16 pack + [B,H,T,D] transpose
    {
        dim3 grid(QKVDIM / BN, MROWS / BM);
        gemm_qkv<<<grid, 256, GSMEM>>>(xh, xl, wqh, wql, rope,
                                       qh16, ql16, kh16, vh16);
    }

    // 2) flash attention -> bf16 hi/lo (ah, al)
    {
        dim3 grid(SEQ / 128, NHEADS, BATCH);
        attn_mma<<<grid, 256, AT_SMEM>>>(qh16, ql16, kh16, vh16, ah, al);
    }

    // 3) out = att @ WO^T
    {
        dim3 grid(DMODEL / BN, MROWS / BM);
        gemm_mma<<<grid, 256, GSMEM>>>(ah, al, wh, wl, out, DMODEL);
    }
}

// round 11
// speedup vs baseline: 2.0993x; 1.3015x over previous
#include <cuda_runtime.h>
#include <cuda_bf16.h>
#include <cuda_fp16.h>
#include <math.h>
#include <stdint.h>

// Problem constants
#define BATCH   2
#define SEQ     2048
#define DMODEL  2048
#define NHEADS  16
#define DHEAD   128
#define MROWS   (BATCH*SEQ)          // 4096
#define QKVDIM  (3*DMODEL)           // 6144
#define KDIM    2048

// Scratch (__device__ globals; allocation-free rule)
__device__ float2 g_rope[(size_t)SEQ * 64];
__device__ __half g_xh[(size_t)MROWS * KDIM],  g_xl[(size_t)MROWS * KDIM];
__device__ __half g_wq16[(size_t)QKVDIM * KDIM];
__device__ __half g_ah[(size_t)MROWS * DMODEL], g_al[(size_t)MROWS * DMODEL];
__device__ __half g_wo16[(size_t)DMODEL * KDIM];
// fp16 attention operands, [B][H][T][D]
#define NATT ((size_t)BATCH * NHEADS * SEQ * DHEAD)
__device__ __half g_qh16[NATT], g_ql16[NATT];
__device__ __half g_kh16[NATT];
__device__ __half g_vh16[NATT];

// ---------------------------------------------------------------------------
// PTX helpers
// ---------------------------------------------------------------------------
static __device__ __forceinline__ uint32_t smem_u32(const void* p) {
    uint32_t a;
    asm("{ .reg .u64 t; cvta.to.shared.u64 t, %1; cvt.u32.u64 %0, t; }" : "=r"(a) : "l"(p));
    return a;
}
static __device__ __forceinline__ void cpasync16(uint32_t dst, const void* src) {
    asm volatile("cp.async.cg.shared.global [%0], [%1], 16;\n" :: "r"(dst), "l"(src));
}
#define CP_COMMIT() asm volatile("cp.async.commit_group;\n" ::: "memory")
#define CP_WAIT0()  asm volatile("cp.async.wait_group 0;\n" ::: "memory")
#define CP_WAIT1()  asm volatile("cp.async.wait_group 1;\n" ::: "memory")

static __device__ __forceinline__ void ldsm_x4(uint32_t& r0, uint32_t& r1,
                                               uint32_t& r2, uint32_t& r3, uint32_t a) {
    asm volatile("ldmatrix.sync.aligned.m8n8.x4.shared.b16 {%0,%1,%2,%3}, [%4];"
                 : "=r"(r0), "=r"(r1), "=r"(r2), "=r"(r3) : "r"(a));
}
static __device__ __forceinline__ void ldsm_x4t(uint32_t& r0, uint32_t& r1,
                                                uint32_t& r2, uint32_t& r3, uint32_t a) {
    asm volatile("ldmatrix.sync.aligned.m8n8.x4.trans.shared.b16 {%0,%1,%2,%3}, [%4];"
                 : "=r"(r0), "=r"(r1), "=r"(r2), "=r"(r3) : "r"(a));
}
static __device__ __forceinline__ void mma_f16(float* c, const uint32_t* a,
                                               uint32_t b0, uint32_t b1) {
    asm volatile(
        "mma.sync.aligned.m16n8k16.row.col.f32.f16.f16.f32 "
        "{%0,%1,%2,%3}, {%4,%5,%6,%7}, {%8,%9}, {%0,%1,%2,%3};"
        : "+f"(c[0]), "+f"(c[1]), "+f"(c[2]), "+f"(c[3])
        : "r"(a[0]), "r"(a[1]), "r"(a[2]), "r"(a[3]), "r"(b0), "r"(b1));
}
static __device__ __forceinline__ void pack_hl(float f0, float f1, uint32_t& hi, uint32_t& lo) {
    __half2 h = __floats2half2_rn(f0, f1);
    float2 fb = __half22float2(h);
    __half2 l2 = __floats2half2_rn(f0 - fb.x, f1 - fb.y);
    hi = *reinterpret_cast<uint32_t*>(&h);
    lo = *reinterpret_cast<uint32_t*>(&l2);
}
static __device__ __forceinline__ uint32_t ex2_f16x2(float a, float b) {
    uint32_t d;
    asm("{ .reg .b32 t;\n cvt.rn.f16x2.f32 t, %2, %1;\n ex2.approx.f16x2 %0, t;\n}"
        : "=r"(d) : "f"(a), "f"(b));
    return d;
}

// ---------------------------------------------------------------------------
// fp32 -> fp16 hi/lo split, vectorized x4
// ---------------------------------------------------------------------------
__global__ __launch_bounds__(256) void split16_kernel(
    const float4* __restrict__ s, uint2* __restrict__ hi,
    uint2* __restrict__ lo, int n4)
{
    int i = blockIdx.x * 256 + threadIdx.x;
    if (i >= n4) return;
    float4 v = s[i];
    __half2 h01 = __floats2half2_rn(v.x, v.y);
    __half2 h23 = __floats2half2_rn(v.z, v.w);
    float2 f01 = __half22float2(h01);
    float2 f23 = __half22float2(h23);
    __half2 l01 = __floats2half2_rn(v.x - f01.x, v.y - f01.y);
    __half2 l23 = __floats2half2_rn(v.z - f23.x, v.w - f23.y);
    uint2 hv, lv;
    hv.x = *reinterpret_cast<uint32_t*>(&h01); hv.y = *reinterpret_cast<uint32_t*>(&h23);
    lv.x = *reinterpret_cast<uint32_t*>(&l01); lv.y = *reinterpret_cast<uint32_t*>(&l23);
    hi[i] = hv;
    lo[i] = lv;
}

// fp32 -> fp16 single, vectorized x4
__global__ __launch_bounds__(256) void cvt16_kernel(
    const float4* __restrict__ s, uint2* __restrict__ d, int n4)
{
    int i = blockIdx.x * 256 + threadIdx.x;
    if (i >= n4) return;
    float4 v = s[i];
    __half2 h01 = __floats2half2_rn(v.x, v.y);
    __half2 h23 = __floats2half2_rn(v.z, v.w);
    uint2 dv;
    dv.x = *reinterpret_cast<uint32_t*>(&h01); dv.y = *reinterpret_cast<uint32_t*>(&h23);
    d[i] = dv;
}

// ---------------------------------------------------------------------------
// RoPE cos/sin table
// ---------------------------------------------------------------------------
__global__ __launch_bounds__(256) void rope_table_kernel(float2* __restrict__ tab)
{
    int idx = blockIdx.x * 256 + threadIdx.x;
    int i = idx & 63, t = idx >> 6;
    double freq = exp(-9.210340371976184 * (double)(2 * i) / 128.0);
    double sd, cd;
    sincos((double)t * freq, &sd, &cd);
    tab[idx] = make_float2((float)cd, (float)sd);
}

// ---------------------------------------------------------------------------
// GEMM mainloop (NT, fp16 2-term: C = (Ah+Al) * B^T), round-6 pipeline shape.
// BM=BN=128, BK=32, 256 threads, 8 warps (2m x 4n), warp tile 64x32, occ 2.
// ---------------------------------------------------------------------------
#define BM 128
#define BN 128
#define BK 32
#define SROW 40
#define PART_BYTES (128 * SROW * 2)          // 10240
#define AH_OFF 0
#define AL_OFF PART_BYTES
#define BH_OFF (2 * PART_BYTES)
#define STG_BYTES (3 * PART_BYTES)           // 30720
#define GSMEM (2 * STG_BYTES)                // 61440

static __device__ __forceinline__ void g_load_stage(
    uint32_t sb, int buf, int s, int bm, int bn, int tid,
    const __half* __restrict__ Ah, const __half* __restrict__ Al,
    const __half* __restrict__ B)
{
    uint32_t base = sb + buf * STG_BYTES;
    const int k0 = s * BK;
    // 1536 16B-chunks: Ah [0,512), Al [512,1024), B [1024,1536)
#pragma unroll
    for (int it = 0; it < 6; it++) {
        int idx = tid + it * 256;
        int part = idx >> 9;                 // uniform per it
        int rem = idx & 511;
        int r = rem >> 2, ch = rem & 3;
        uint32_t so = part * PART_BYTES + r * (SROW * 2) + ch * 16;
        const __half* src = (part == 0) ? Ah : (part == 1) ? Al : B;
        int row = (part == 2) ? (bn + r) : (bm + r);
        cpasync16(base + so, src + (size_t)row * KDIM + k0 + ch * 8);
    }
    CP_COMMIT();
}

static __device__ __forceinline__ void g_mainloop(
    uint32_t sb, int bm, int bn, int tid, int lane, int wm, int wn,
    const __half* __restrict__ Ah, const __half* __restrict__ Al,
    const __half* __restrict__ B,
    float acc[4][4][4])
{
    const uint32_t aRow = wm * 64 + (lane & 15);
    const uint32_t aCol = (lane >> 4) << 3;
    const uint32_t bOff = (wn * 32 + (lane & 7) + ((lane & 16) >> 1)) * (SROW * 2)
                        + (((lane >> 3) & 1) << 3) * 2;

    g_load_stage(sb, 0, 0, bm, bn, tid, Ah, Al, B);

    const int NS = KDIM / BK;
    for (int s = 0; s < NS; s++) {
        const int buf = s & 1;
        if (s + 1 < NS) {
            g_load_stage(sb, buf ^ 1, s + 1, bm, bn, tid, Ah, Al, B);
            CP_WAIT1();
        } else {
            CP_WAIT0();
        }
        __syncthreads();

        uint32_t base = sb + buf * STG_BYTES;
#pragma unroll
        for (int kk = 0; kk < BK; kk += 16) {
            uint32_t af[4][4], bf[4][2];
#pragma unroll
            for (int mt = 0; mt < 4; mt++)
                ldsm_x4(af[mt][0], af[mt][1], af[mt][2], af[mt][3],
                        base + AH_OFF + (aRow + mt * 16) * (SROW * 2) + (aCol + kk) * 2);
#pragma unroll
            for (int np = 0; np < 2; np++)
                ldsm_x4(bf[2*np][0], bf[2*np][1], bf[2*np+1][0], bf[2*np+1][1],
                        base + BH_OFF + bOff + np * 16 * (SROW * 2) + kk * 2);
            // Ah x B
#pragma unroll
            for (int mt = 0; mt < 4; mt++)
#pragma unroll
                for (int nt = 0; nt < 4; nt++)
                    mma_f16(acc[mt][nt], af[mt], bf[nt][0], bf[nt][1]);
            // Al x B
#pragma unroll
            for (int mt = 0; mt < 4; mt++)
                ldsm_x4(af[mt][0], af[mt][1], af[mt][2], af[mt][3],
                        base + AL_OFF + (aRow + mt * 16) * (SROW * 2) + (aCol + kk) * 2);
#pragma unroll
            for (int mt = 0; mt < 4; mt++)
#pragma unroll
                for (int nt = 0; nt < 4; nt++)
                    mma_f16(acc[mt][nt], af[mt], bf[nt][0], bf[nt][1]);
        }
        __syncthreads();
    }
}

// Plain fp32-output GEMM (WO projection)
__global__ __launch_bounds__(256, 2) void gemm_mma(
    const __half* __restrict__ Ah, const __half* __restrict__ Al,
    const __half* __restrict__ B,
    float* __restrict__ C, int ldc)
{
    extern __shared__ char smem[];
    uint32_t sb = smem_u32(smem);
    const int tid = threadIdx.x, wid = tid >> 5, lane = tid & 31;
    const int wm = wid >> 2, wn = wid & 3;
    const int bm = blockIdx.y * BM, bn = blockIdx.x * BN;

    float acc[4][4][4];
#pragma unroll
    for (int i = 0; i < 4; i++)
#pragma unroll
        for (int j = 0; j < 4; j++)
#pragma unroll
            for (int e = 0; e < 4; e++) acc[i][j][e] = 0.f;

    g_mainloop(sb, bm, bn, tid, lane, wm, wn, Ah, Al, B, acc);

    const int r0 = bm + wm * 64 + (lane >> 2);
    const int c0 = bn + wn * 32 + 2 * (lane & 3);
#pragma unroll
    for (int mt = 0; mt < 4; mt++)
#pragma unroll
        for (int nt = 0; nt < 4; nt++) {
            float2 v0 = make_float2(acc[mt][nt][0], acc[mt][nt][1]);
            float2 v1 = make_float2(acc[mt][nt][2], acc[mt][nt][3]);
            *reinterpret_cast<float2*>(&C[(size_t)(r0 + mt * 16)     * ldc + c0 + nt * 8]) = v0;
            *reinterpret_cast<float2*>(&C[(size_t)(r0 + mt * 16 + 8) * ldc + c0 + nt * 8]) = v1;
        }
}

// QKV GEMM with fused RoPE + fp16 pack + [B,H,T,D] transpose epilogue.
__global__ __launch_bounds__(256, 2) void gemm_qkv(
    const __half* __restrict__ Ah, const __half* __restrict__ Al,
    const __half* __restrict__ B,
    const float2* __restrict__ tab,
    __half* __restrict__ Qh, __half* __restrict__ Ql,
    __half* __restrict__ Kh, __half* __restrict__ Vh)
{
    extern __shared__ char smem[];
    uint32_t sb = smem_u32(smem);
    const int tid = threadIdx.x, wid = tid >> 5, lane = tid & 31;
    const int wm = wid >> 2, wn = wid & 3;
    const int bm = blockIdx.y * BM, bn = blockIdx.x * BN;

    float acc[4][4][4];
#pragma unroll
    for (int i = 0; i < 4; i++)
#pragma unroll
        for (int j = 0; j < 4; j++)
#pragma unroll
            for (int e = 0; e < 4; e++) acc[i][j][e] = 0.f;

    g_mainloop(sb, bm, bn, tid, lane, wm, wn, Ah, Al, B, acc);

    const int mat  = bn >> 11;                  // 0=Q,1=K,2=V
    const int head = (bn >> 7) & (NHEADS - 1);
    const float QSCL = 0.1275174456f;           // log2(e)/sqrt(128)

    const int r0 = bm + wm * 64 + (lane >> 2);
    const int c0 = (bn & 127) + wn * 32 + 2 * (lane & 3);
    const int b  = r0 >> 11;
    const size_t obase = ((size_t)(b * NHEADS + head)) * SEQ * DHEAD;

#pragma unroll
    for (int mt = 0; mt < 4; mt++) {
        const int tA = (r0 + mt * 16) & (SEQ - 1);
        const int tB = tA + 8;
#pragma unroll
        for (int nt = 0; nt < 4; nt++) {
            const int d = c0 + nt * 8;
            float x0 = acc[mt][nt][0], x1 = acc[mt][nt][1];
            float y0 = acc[mt][nt][2], y1 = acc[mt][nt][3];
            if (mat < 2) {
                float2 csA = tab[tA * 64 + (d >> 1)];
                float2 csB = tab[tB * 64 + (d >> 1)];
                float nx0 = x0 * csA.x - x1 * csA.y;
                float nx1 = x1 * csA.x + x0 * csA.y;
                float ny0 = y0 * csB.x - y1 * csB.y;
                float ny1 = y1 * csB.x + y0 * csB.y;
                x0 = nx0; x1 = nx1; y0 = ny0; y1 = ny1;
                if (mat == 0) { x0 *= QSCL; x1 *= QSCL; y0 *= QSCL; y1 *= QSCL; }
            }
            size_t dA = obase + (size_t)tA * DHEAD + d;
            size_t dB = obase + (size_t)tB * DHEAD + d;
            if (mat == 0) {
                uint32_t hi, lo;
                pack_hl(x0, x1, hi, lo);
                *reinterpret_cast<uint32_t*>(Qh + dA) = hi;
                *reinterpret_cast<uint32_t*>(Ql + dA) = lo;
                pack_hl(y0, y1, hi, lo);
                *reinterpret_cast<uint32_t*>(Qh + dB) = hi;
                *reinterpret_cast<uint32_t*>(Ql + dB) = lo;
            } else {
                __half* D = (mat == 1) ? Kh : Vh;
                __half2 v0 = __floats2half2_rn(x0, x1);
                __half2 v1 = __floats2half2_rn(y0, y1);
                *reinterpret_cast<__half2*>(D + dA) = v0;
                *reinterpret_cast<__half2*>(D + dB) = v1;
            }
        }
    }
}

// ---------------------------------------------------------------------------
// Flash attention — unchanged from round 10 except fp16 hi/lo output.
// ---------------------------------------------------------------------------
#define AT_SROWB 272
#define SM_QH 0
#define SM_QL 34816
#define SM_K  69632
#define SM_V  104448
#define KPART 17408
#define AT_SMEM 139264

static __device__ __forceinline__ void at_load_kv(
    uint32_t sb, int buf, int kt, size_t bh, int tid,
    const __half* __restrict__ Kh, const __half* __restrict__ Vh)
{
    const int k0 = kt * 64;
#pragma unroll
    for (int it = 0; it < 8; it++) {
        int idx = tid + it * 256;
        int part = idx >> 10;               // 0:Kh 1:Vh
        int rem = idx & 1023;
        int r = rem >> 4, ch = rem & 15;
        const __half* src = (part == 0) ? Kh : Vh;
        uint32_t dbase = ((part == 0) ? SM_K : SM_V) + buf * KPART;
        cpasync16(sb + dbase + r * AT_SROWB + ch * 16,
                  src + ((size_t)(bh + k0 + r)) * DHEAD + ch * 8);
    }
    CP_COMMIT();
}

__global__ __launch_bounds__(256, 1) void attn_mma(
    const __half* __restrict__ Qh, const __half* __restrict__ Ql,
    const __half* __restrict__ Kh, const __half* __restrict__ Vh,
    __half* __restrict__ Oh, __half* __restrict__ Ol)
{
    extern __shared__ char smem[];
    uint32_t sb = smem_u32(smem);
    const int tid = threadIdx.x, lane = tid & 31, w = tid >> 5;
    const int qt = gridDim.x - 1 - blockIdx.x;
    const int h = blockIdx.y, b = blockIdx.z;
    const int q0 = qt * 128;
    const size_t bh = (size_t)(b * NHEADS + h) * SEQ;

    // Q load (group A)
    {
        const __half* gq0 = Qh + (bh + q0) * DHEAD;
        const __half* gq1 = Ql + (bh + q0) * DHEAD;
#pragma unroll
        for (int it = 0; it < 16; it++) {
            int idx = tid + it * 256;
            int part = idx >> 11, rem = idx & 2047;
            int r = rem >> 4, ch = rem & 15;
            const __half* src = part ? gq1 : gq0;
            cpasync16(sb + SM_QH + part * 34816 + r * AT_SROWB + ch * 16,
                      src + (size_t)r * DHEAD + ch * 8);
        }
        CP_COMMIT();
    }
    at_load_kv(sb, 0, 0, bh, tid, Kh, Vh);   // group B

    // Hoist Q fragments to registers.
    const uint32_t qha = sb + SM_QH + (w * 16 + (lane & 15)) * AT_SROWB + (((uint32_t)lane >> 4) << 3) * 2;
    const uint32_t qla = qha + 34816;
    uint32_t qhf[8][4], qlf[8][4];
    CP_WAIT1();
    __syncthreads();
#pragma unroll
    for (int ks = 0; ks < 8; ks++) {
        ldsm_x4(qhf[ks][0], qhf[ks][1], qhf[ks][2], qhf[ks][3], qha + ks * 32);
        ldsm_x4(qlf[ks][0], qlf[ks][1], qlf[ks][2], qlf[ks][3], qla + ks * 32);
    }

    float m[2] = {-1e30f, -1e30f}, l[2] = {0.f, 0.f};
    float O[16][4];
#pragma unroll
    for (int i = 0; i < 16; i++)
#pragma unroll
        for (int e = 0; e < 4; e++) O[i][e] = 0.f;

    const uint32_t koff = ((lane & 7) + ((lane & 16) >> 1)) * AT_SROWB + (((lane >> 3) & 1) << 3) * 2;
    const uint32_t voff = (lane & 15) * AT_SROWB + (((uint32_t)lane >> 4) << 3) * 2;
    const uint32_t ONES = 0x3C003C00u;

    const int nkt = 2 * qt + 2;
    for (int kt = 0; kt < nkt; kt++) {
        const int buf = kt & 1;
        __syncthreads();
        if (kt + 1 < nkt) {
            at_load_kv(sb, buf ^ 1, kt + 1, bh, tid, Kh, Vh);
            CP_WAIT1();
        } else {
            CP_WAIT0();
        }
        __syncthreads();

        // ---- S = Q K^T (2-term: Qh*Kh + Ql*Kh), Q from registers ----
        float sacc[8][4];
#pragma unroll
        for (int nt = 0; nt < 8; nt++)
#pragma unroll
            for (int e = 0; e < 4; e++) sacc[nt][e] = 0.f;

        const uint32_t kbase = sb + SM_K + buf * KPART;
#pragma unroll
        for (int ks = 0; ks < 8; ks++) {
#pragma unroll
            for (int np = 0; np < 4; np++) {
                uint32_t k0r, k1r, k2r, k3r;
                ldsm_x4(k0r, k1r, k2r, k3r,
                        kbase + koff + np * 16 * AT_SROWB + ks * 32);
                mma_f16(sacc[2*np],   qhf[ks], k0r, k1r);
                mma_f16(sacc[2*np],   qlf[ks], k0r, k1r);
                mma_f16(sacc[2*np+1], qhf[ks], k2r, k3r);
                mma_f16(sacc[2*np+1], qlf[ks], k2r, k3r);
            }
        }

        // ---- causal mask (diagonal tiles only) ----
        const int k0 = kt * 64;
        if (k0 + 63 > q0 + w * 16) {
            const int rA = q0 + w * 16 + (lane >> 2);
#pragma unroll
            for (int nt = 0; nt < 8; nt++) {
                int c = k0 + nt * 8 + 2 * (lane & 3);
                if (c     > rA)     sacc[nt][0] = -1e30f;
                if (c + 1 > rA)     sacc[nt][1] = -1e30f;
                if (c     > rA + 8) sacc[nt][2] = -1e30f;
                if (c + 1 > rA + 8) sacc[nt][3] = -1e30f;
            }
        }

        // ---- online softmax (log2 units) ----
        float mx0 = sacc[0][0], mx1 = sacc[0][2];
#pragma unroll
        for (int nt = 0; nt < 8; nt++) {
            mx0 = fmaxf(mx0, fmaxf(sacc[nt][0], sacc[nt][1]));
            mx1 = fmaxf(mx1, fmaxf(sacc[nt][2], sacc[nt][3]));
        }
        mx0 = fmaxf(mx0, __shfl_xor_sync(0xffffffffu, mx0, 1));
        mx0 = fmaxf(mx0, __shfl_xor_sync(0xffffffffu, mx0, 2));
        mx1 = fmaxf(mx1, __shfl_xor_sync(0xffffffffu, mx1, 1));
        mx1 = fmaxf(mx1, __shfl_xor_sync(0xffffffffu, mx1, 2));
        const float mn0 = fmaxf(m[0], mx0), mn1 = fmaxf(m[1], mx1);
        const float fac0 = exp2f(m[0] - mn0), fac1 = exp2f(m[1] - mn1);
        m[0] = mn0; m[1] = mn1;

        // ---- P = 2^(s - mn) as fp16 A-fragments ----
        uint32_t aPh[4][4];
#pragma unroll
        for (int ks = 0; ks < 4; ks++) {
            aPh[ks][0] = ex2_f16x2(sacc[2*ks][0]   - mn0, sacc[2*ks][1]   - mn0);
            aPh[ks][1] = ex2_f16x2(sacc[2*ks][2]   - mn1, sacc[2*ks][3]   - mn1);
            aPh[ks][2] = ex2_f16x2(sacc[2*ks+1][0] - mn0, sacc[2*ks+1][1] - mn0);
            aPh[ks][3] = ex2_f16x2(sacc[2*ks+1][2] - mn1, sacc[2*ks+1][3] - mn1);
        }

        // ---- rescale O; O += P Vh; l via ones-mma ----
#pragma unroll
        for (int i = 0; i < 16; i++) {
            O[i][0] *= fac0; O[i][1] *= fac0;
            O[i][2] *= fac1; O[i][3] *= fac1;
        }
        float Olsum[4] = {0.f, 0.f, 0.f, 0.f};
        const uint32_t vbase = sb + SM_V + buf * KPART;
#pragma unroll
        for (int ks = 0; ks < 4; ks++) {
            mma_f16(Olsum, aPh[ks], ONES, ONES);
#pragma unroll
            for (int dt = 0; dt < 8; dt++) {
                uint32_t va = vbase + voff + ks * 16 * AT_SROWB + dt * 32;
                uint32_t vh0, vh1, vh2, vh3;
                ldsm_x4t(vh0, vh1, vh2, vh3, va);
                mma_f16(O[2*dt],   aPh[ks], vh0, vh1);
                mma_f16(O[2*dt+1], aPh[ks], vh2, vh3);
            }
        }
        l[0] = l[0] * fac0 + Olsum[0];
        l[1] = l[1] * fac1 + Olsum[2];
    }

    // ---- normalize & write fp16 hi/lo to [b, t, h*128+d] ----
    const float inv0 = 1.f / l[0], inv1 = 1.f / l[1];
    const int rowA = q0 + w * 16 + (lane >> 2);
    const size_t baseA = ((size_t)b * SEQ + rowA) * DMODEL + h * DHEAD;
    const size_t baseB = baseA + (size_t)8 * DMODEL;
#pragma unroll
    for (int nt = 0; nt < 16; nt++) {
        int d = nt * 8 + 2 * (lane & 3);
        float o0 = O[nt][0] * inv0, o1 = O[nt][1] * inv0;
        float o2 = O[nt][2] * inv1, o3 = O[nt][3] * inv1;
        uint32_t hi, lo;
        pack_hl(o0, o1, hi, lo);
        *reinterpret_cast<uint32_t*>(Oh + baseA + d) = hi;
        *reinterpret_cast<uint32_t*>(Ol + baseA + d) = lo;
        pack_hl(o2, o3, hi, lo);
        *reinterpret_cast<uint32_t*>(Oh + baseB + d) = hi;
        *reinterpret_cast<uint32_t*>(Ol + baseB + d) = lo;
    }
}

// ---------------------------------------------------------------------------
extern "C" void kernel_launch(void* const* d_in, const int* in_sizes, int n_in,
                              void* d_out, int out_size)
{
    const float* x    = (const float*)d_in[0];
    const float* Wqkv = (const float*)d_in[1];
    const float* WO   = (const float*)d_in[2];
    float* out = (float*)d_out;

    float2* rope;
    cudaGetSymbolAddress((void**)&rope, g_rope);
    __half *xh, *xl, *wq16, *ah, *al, *wo16;
    cudaGetSymbolAddress((void**)&xh, g_xh);     cudaGetSymbolAddress((void**)&xl, g_xl);
    cudaGetSymbolAddress((void**)&wq16, g_wq16);
    cudaGetSymbolAddress((void**)&ah, g_ah);     cudaGetSymbolAddress((void**)&al, g_al);
    cudaGetSymbolAddress((void**)&wo16, g_wo16);
    __half *qh16, *ql16, *kh16, *vh16;
    cudaGetSymbolAddress((void**)&qh16, g_qh16); cudaGetSymbolAddress((void**)&ql16, g_ql16);
    cudaGetSymbolAddress((void**)&kh16, g_kh16); cudaGetSymbolAddress((void**)&vh16, g_vh16);

    cudaFuncSetAttribute(gemm_mma, cudaFuncAttributeMaxDynamicSharedMemorySize, GSMEM);
    cudaFuncSetAttribute(gemm_qkv, cudaFuncAttributeMaxDynamicSharedMemorySize, GSMEM);
    cudaFuncSetAttribute(attn_mma, cudaFuncAttributeMaxDynamicSharedMemorySize, AT_SMEM);

    rope_table_kernel<<<(SEQ * 64) / 256, 256>>>(rope);
    { int n4 = (MROWS * KDIM) / 4;
      split16_kernel<<<(n4 + 255) / 256, 256>>>((const float4*)x, (uint2*)xh, (uint2*)xl, n4); }
    { int n4 = (QKVDIM * KDIM) / 4;
      cvt16_kernel<<<(n4 + 255) / 256, 256>>>((const float4*)Wqkv, (uint2*)wq16, n4); }
    { int n4 = (DMODEL * KDIM) / 4;
      cvt16_kernel<<<(n4 + 255) / 256, 256>>>((const float4*)WO, (uint2*)wo16, n4); }

    // 1) QKV GEMM with fused RoPE + fp16 pack + [B,H,T,D] transpose
    {
        dim3 grid(QKVDIM / BN, MROWS / BM);
        gemm_qkv<<<grid, 256, GSMEM>>>(xh, xl, wq16, rope,
                                       qh16, ql16, kh16, vh16);
    }

    // 2) flash attention -> fp16 hi/lo (ah, al)
    {
        dim3 grid(SEQ / 128, NHEADS, BATCH);
        attn_mma<<<grid, 256, AT_SMEM>>>(qh16, ql16, kh16, vh16, ah, al);
    }

    // 3) out = att @ WO^T
    {
        dim3 grid(DMODEL / BN, MROWS / BM);
        gemm_mma<<<grid, 256, GSMEM>>>(ah, al, wo16, out, DMODEL);
    }
}

// round 12
// speedup vs baseline: 3.0775x; 1.4660x over previous
#include <cuda_runtime.h>
#include <cuda_bf16.h>
#include <cuda_fp16.h>
#include <math.h>
#include <stdint.h>

// Problem constants
#define BATCH   2
#define SEQ     2048
#define DMODEL  2048
#define NHEADS  16
#define DHEAD   128
#define MROWS   (BATCH*SEQ)          // 4096
#define QKVDIM  (3*DMODEL)           // 6144
#define KDIM    2048

// Scratch (__device__ globals; allocation-free rule)
__device__ float2 g_rope[(size_t)SEQ * 64];
__device__ __half g_x16[(size_t)MROWS * KDIM];
__device__ __half g_wq16[(size_t)QKVDIM * KDIM];
__device__ __half g_a16[(size_t)MROWS * DMODEL];
__device__ __half g_wo16[(size_t)DMODEL * KDIM];
// fp16 attention operands, [B][H][T][D]
#define NATT ((size_t)BATCH * NHEADS * SEQ * DHEAD)
__device__ __half g_qh16[NATT], g_ql16[NATT];
__device__ __half g_kh16[NATT];
__device__ __half g_vh16[NATT];

// ---------------------------------------------------------------------------
// PTX helpers
// ---------------------------------------------------------------------------
static __device__ __forceinline__ uint32_t smem_u32(const void* p) {
    uint32_t a;
    asm("{ .reg .u64 t; cvta.to.shared.u64 t, %1; cvt.u32.u64 %0, t; }" : "=r"(a) : "l"(p));
    return a;
}
static __device__ __forceinline__ void cpasync16(uint32_t dst, const void* src) {
    asm volatile("cp.async.cg.shared.global [%0], [%1], 16;\n" :: "r"(dst), "l"(src));
}
#define CP_COMMIT() asm volatile("cp.async.commit_group;\n" ::: "memory")
#define CP_WAIT0()  asm volatile("cp.async.wait_group 0;\n" ::: "memory")
#define CP_WAIT1()  asm volatile("cp.async.wait_group 1;\n" ::: "memory")

static __device__ __forceinline__ void ldsm_x4(uint32_t& r0, uint32_t& r1,
                                               uint32_t& r2, uint32_t& r3, uint32_t a) {
    asm volatile("ldmatrix.sync.aligned.m8n8.x4.shared.b16 {%0,%1,%2,%3}, [%4];"
                 : "=r"(r0), "=r"(r1), "=r"(r2), "=r"(r3) : "r"(a));
}
static __device__ __forceinline__ void ldsm_x4t(uint32_t& r0, uint32_t& r1,
                                                uint32_t& r2, uint32_t& r3, uint32_t a) {
    asm volatile("ldmatrix.sync.aligned.m8n8.x4.trans.shared.b16 {%0,%1,%2,%3}, [%4];"
                 : "=r"(r0), "=r"(r1), "=r"(r2), "=r"(r3) : "r"(a));
}
static __device__ __forceinline__ void mma_f16(float* c, const uint32_t* a,
                                               uint32_t b0, uint32_t b1) {
    asm volatile(
        "mma.sync.aligned.m16n8k16.row.col.f32.f16.f16.f32 "
        "{%0,%1,%2,%3}, {%4,%5,%6,%7}, {%8,%9}, {%0,%1,%2,%3};"
        : "+f"(c[0]), "+f"(c[1]), "+f"(c[2]), "+f"(c[3])
        : "r"(a[0]), "r"(a[1]), "r"(a[2]), "r"(a[3]), "r"(b0), "r"(b1));
}
static __device__ __forceinline__ void pack_hl(float f0, float f1, uint32_t& hi, uint32_t& lo) {
    __half2 h = __floats2half2_rn(f0, f1);
    float2 fb = __half22float2(h);
    __half2 l2 = __floats2half2_rn(f0 - fb.x, f1 - fb.y);
    hi = *reinterpret_cast<uint32_t*>(&h);
    lo = *reinterpret_cast<uint32_t*>(&l2);
}
static __device__ __forceinline__ uint32_t ex2_f16x2(float a, float b) {
    uint32_t d;
    asm("{ .reg .b32 t;\n cvt.rn.f16x2.f32 t, %2, %1;\n ex2.approx.f16x2 %0, t;\n}"
        : "=r"(d) : "f"(a), "f"(b));
    return d;
}

// ---------------------------------------------------------------------------
// fp32 -> fp16, vectorized x4
// ---------------------------------------------------------------------------
__global__ __launch_bounds__(256) void cvt16_kernel(
    const float4* __restrict__ s, uint2* __restrict__ d, int n4)
{
    int i = blockIdx.x * 256 + threadIdx.x;
    if (i >= n4) return;
    float4 v = s[i];
    __half2 h01 = __floats2half2_rn(v.x, v.y);
    __half2 h23 = __floats2half2_rn(v.z, v.w);
    uint2 dv;
    dv.x = *reinterpret_cast<uint32_t*>(&h01); dv.y = *reinterpret_cast<uint32_t*>(&h23);
    d[i] = dv;
}

// ---------------------------------------------------------------------------
// RoPE cos/sin table
// ---------------------------------------------------------------------------
__global__ __launch_bounds__(256) void rope_table_kernel(float2* __restrict__ tab)
{
    int idx = blockIdx.x * 256 + threadIdx.x;
    int i = idx & 63, t = idx >> 6;
    double freq = exp(-9.210340371976184 * (double)(2 * i) / 128.0);
    double sd, cd;
    sincos((double)t * freq, &sd, &cd);
    tab[idx] = make_float2((float)cd, (float)sd);
}

// ---------------------------------------------------------------------------
// GEMM mainloop (NT, fp16 1-term: C = A * B^T), round-6 pipeline shape.
// BM=BN=128, BK=32, 256 threads, 8 warps (2m x 4n), warp tile 64x32, occ 2.
// ---------------------------------------------------------------------------
#define BM 128
#define BN 128
#define BK 32
#define SROW 40
#define PART_BYTES (128 * SROW * 2)          // 10240
#define A_OFF 0
#define B_OFF PART_BYTES
#define STG_BYTES (2 * PART_BYTES)           // 20480
#define GSMEM (2 * STG_BYTES)                // 40960

static __device__ __forceinline__ void g_load_stage(
    uint32_t sb, int buf, int s, int bm, int bn, int tid,
    const __half* __restrict__ A, const __half* __restrict__ B)
{
    uint32_t base = sb + buf * STG_BYTES;
    const int k0 = s * BK;
    // 1024 16B-chunks: A [0,512), B [512,1024)
#pragma unroll
    for (int it = 0; it < 4; it++) {
        int idx = tid + it * 256;
        int part = idx >> 9;                 // uniform per it
        int rem = idx & 511;
        int r = rem >> 2, ch = rem & 3;
        const __half* src = part ? B : A;
        int row = part ? (bn + r) : (bm + r);
        cpasync16(base + part * PART_BYTES + r * (SROW * 2) + ch * 16,
                  src + (size_t)row * KDIM + k0 + ch * 8);
    }
    CP_COMMIT();
}

static __device__ __forceinline__ void g_mainloop(
    uint32_t sb, int bm, int bn, int tid, int lane, int wm, int wn,
    const __half* __restrict__ A, const __half* __restrict__ B,
    float acc[4][4][4])
{
    const uint32_t aRow = wm * 64 + (lane & 15);
    const uint32_t aCol = (lane >> 4) << 3;
    const uint32_t bOff = (wn * 32 + (lane & 7) + ((lane & 16) >> 1)) * (SROW * 2)
                        + (((lane >> 3) & 1) << 3) * 2;

    g_load_stage(sb, 0, 0, bm, bn, tid, A, B);

    const int NS = KDIM / BK;
    for (int s = 0; s < NS; s++) {
        const int buf = s & 1;
        if (s + 1 < NS) {
            g_load_stage(sb, buf ^ 1, s + 1, bm, bn, tid, A, B);
            CP_WAIT1();
        } else {
            CP_WAIT0();
        }
        __syncthreads();

        uint32_t base = sb + buf * STG_BYTES;
#pragma unroll
        for (int kk = 0; kk < BK; kk += 16) {
            uint32_t af[4][4], bf[4][2];
#pragma unroll
            for (int mt = 0; mt < 4; mt++)
                ldsm_x4(af[mt][0], af[mt][1], af[mt][2], af[mt][3],
                        base + A_OFF + (aRow + mt * 16) * (SROW * 2) + (aCol + kk) * 2);
#pragma unroll
            for (int np = 0; np < 2; np++)
                ldsm_x4(bf[2*np][0], bf[2*np][1], bf[2*np+1][0], bf[2*np+1][1],
                        base + B_OFF + bOff + np * 16 * (SROW * 2) + kk * 2);
#pragma unroll
            for (int mt = 0; mt < 4; mt++)
#pragma unroll
                for (int nt = 0; nt < 4; nt++)
                    mma_f16(acc[mt][nt], af[mt], bf[nt][0], bf[nt][1]);
        }
        __syncthreads();
    }
}

// Plain fp32-output GEMM (WO projection)
__global__ __launch_bounds__(256, 2) void gemm_mma(
    const __half* __restrict__ A, const __half* __restrict__ B,
    float* __restrict__ C, int ldc)
{
    extern __shared__ char smem[];
    uint32_t sb = smem_u32(smem);
    const int tid = threadIdx.x, wid = tid >> 5, lane = tid & 31;
    const int wm = wid >> 2, wn = wid & 3;
    const int bm = blockIdx.y * BM, bn = blockIdx.x * BN;

    float acc[4][4][4];
#pragma unroll
    for (int i = 0; i < 4; i++)
#pragma unroll
        for (int j = 0; j < 4; j++)
#pragma unroll
            for (int e = 0; e < 4; e++) acc[i][j][e] = 0.f;

    g_mainloop(sb, bm, bn, tid, lane, wm, wn, A, B, acc);

    const int r0 = bm + wm * 64 + (lane >> 2);
    const int c0 = bn + wn * 32 + 2 * (lane & 3);
#pragma unroll
    for (int mt = 0; mt < 4; mt++)
#pragma unroll
        for (int nt = 0; nt < 4; nt++) {
            float2 v0 = make_float2(acc[mt][nt][0], acc[mt][nt][1]);
            float2 v1 = make_float2(acc[mt][nt][2], acc[mt][nt][3]);
            *reinterpret_cast<float2*>(&C[(size_t)(r0 + mt * 16)     * ldc + c0 + nt * 8]) = v0;
            *reinterpret_cast<float2*>(&C[(size_t)(r0 + mt * 16 + 8) * ldc + c0 + nt * 8]) = v1;
        }
}

// QKV GEMM with fused RoPE + fp16 pack + [B,H,T,D] transpose epilogue.
__global__ __launch_bounds__(256, 2) void gemm_qkv(
    const __half* __restrict__ A, const __half* __restrict__ B,
    const float2* __restrict__ tab,
    __half* __restrict__ Qh, __half* __restrict__ Ql,
    __half* __restrict__ Kh, __half* __restrict__ Vh)
{
    extern __shared__ char smem[];
    uint32_t sb = smem_u32(smem);
    const int tid = threadIdx.x, wid = tid >> 5, lane = tid & 31;
    const int wm = wid >> 2, wn = wid & 3;
    const int bm = blockIdx.y * BM, bn = blockIdx.x * BN;

    float acc[4][4][4];
#pragma unroll
    for (int i = 0; i < 4; i++)
#pragma unroll
        for (int j = 0; j < 4; j++)
#pragma unroll
            for (int e = 0; e < 4; e++) acc[i][j][e] = 0.f;

    g_mainloop(sb, bm, bn, tid, lane, wm, wn, A, B, acc);

    const int mat  = bn >> 11;                  // 0=Q,1=K,2=V
    const int head = (bn >> 7) & (NHEADS - 1);
    const float QSCL = 0.1275174456f;           // log2(e)/sqrt(128)

    const int r0 = bm + wm * 64 + (lane >> 2);
    const int c0 = (bn & 127) + wn * 32 + 2 * (lane & 3);
    const int b  = r0 >> 11;
    const size_t obase = ((size_t)(b * NHEADS + head)) * SEQ * DHEAD;

#pragma unroll
    for (int mt = 0; mt < 4; mt++) {
        const int tA = (r0 + mt * 16) & (SEQ - 1);
        const int tB = tA + 8;
#pragma unroll
        for (int nt = 0; nt < 4; nt++) {
            const int d = c0 + nt * 8;
            float x0 = acc[mt][nt][0], x1 = acc[mt][nt][1];
            float y0 = acc[mt][nt][2], y1 = acc[mt][nt][3];
            if (mat < 2) {
                float2 csA = tab[tA * 64 + (d >> 1)];
                float2 csB = tab[tB * 64 + (d >> 1)];
                float nx0 = x0 * csA.x - x1 * csA.y;
                float nx1 = x1 * csA.x + x0 * csA.y;
                float ny0 = y0 * csB.x - y1 * csB.y;
                float ny1 = y1 * csB.x + y0 * csB.y;
                x0 = nx0; x1 = nx1; y0 = ny0; y1 = ny1;
                if (mat == 0) { x0 *= QSCL; x1 *= QSCL; y0 *= QSCL; y1 *= QSCL; }
            }
            size_t dA = obase + (size_t)tA * DHEAD + d;
            size_t dB = obase + (size_t)tB * DHEAD + d;
            if (mat == 0) {
                uint32_t hi, lo;
                pack_hl(x0, x1, hi, lo);
                *reinterpret_cast<uint32_t*>(Qh + dA) = hi;
                *reinterpret_cast<uint32_t*>(Ql + dA) = lo;
                pack_hl(y0, y1, hi, lo);
                *reinterpret_cast<uint32_t*>(Qh + dB) = hi;
                *reinterpret_cast<uint32_t*>(Ql + dB) = lo;
            } else {
                __half* D = (mat == 1) ? Kh : Vh;
                __half2 v0 = __floats2half2_rn(x0, x1);
                __half2 v1 = __floats2half2_rn(y0, y1);
                *reinterpret_cast<__half2*>(D + dA) = v0;
                *reinterpret_cast<__half2*>(D + dB) = v1;
            }
        }
    }
}

// ---------------------------------------------------------------------------
// Flash attention — unchanged mainloop; output single fp16 array.
// ---------------------------------------------------------------------------
#define AT_SROWB 272
#define SM_QH 0
#define SM_QL 34816
#define SM_K  69632
#define SM_V  104448
#define KPART 17408
#define AT_SMEM 139264

static __device__ __forceinline__ void at_load_kv(
    uint32_t sb, int buf, int kt, size_t bh, int tid,
    const __half* __restrict__ Kh, const __half* __restrict__ Vh)
{
    const int k0 = kt * 64;
#pragma unroll
    for (int it = 0; it < 8; it++) {
        int idx = tid + it * 256;
        int part = idx >> 10;               // 0:Kh 1:Vh
        int rem = idx & 1023;
        int r = rem >> 4, ch = rem & 15;
        const __half* src = (part == 0) ? Kh : Vh;
        uint32_t dbase = ((part == 0) ? SM_K : SM_V) + buf * KPART;
        cpasync16(sb + dbase + r * AT_SROWB + ch * 16,
                  src + ((size_t)(bh + k0 + r)) * DHEAD + ch * 8);
    }
    CP_COMMIT();
}

__global__ __launch_bounds__(256, 1) void attn_mma(
    const __half* __restrict__ Qh, const __half* __restrict__ Ql,
    const __half* __restrict__ Kh, const __half* __restrict__ Vh,
    __half* __restrict__ O16)
{
    extern __shared__ char smem[];
    uint32_t sb = smem_u32(smem);
    const int tid = threadIdx.x, lane = tid & 31, w = tid >> 5;
    const int qt = gridDim.x - 1 - blockIdx.x;
    const int h = blockIdx.y, b = blockIdx.z;
    const int q0 = qt * 128;
    const size_t bh = (size_t)(b * NHEADS + h) * SEQ;

    // Q load (group A)
    {
        const __half* gq0 = Qh + (bh + q0) * DHEAD;
        const __half* gq1 = Ql + (bh + q0) * DHEAD;
#pragma unroll
        for (int it = 0; it < 16; it++) {
            int idx = tid + it * 256;
            int part = idx >> 11, rem = idx & 2047;
            int r = rem >> 4, ch = rem & 15;
            const __half* src = part ? gq1 : gq0;
            cpasync16(sb + SM_QH + part * 34816 + r * AT_SROWB + ch * 16,
                      src + (size_t)r * DHEAD + ch * 8);
        }
        CP_COMMIT();
    }
    at_load_kv(sb, 0, 0, bh, tid, Kh, Vh);   // group B

    // Hoist Q fragments to registers.
    const uint32_t qha = sb + SM_QH + (w * 16 + (lane & 15)) * AT_SROWB + (((uint32_t)lane >> 4) << 3) * 2;
    const uint32_t qla = qha + 34816;
    uint32_t qhf[8][4], qlf[8][4];
    CP_WAIT1();
    __syncthreads();
#pragma unroll
    for (int ks = 0; ks < 8; ks++) {
        ldsm_x4(qhf[ks][0], qhf[ks][1], qhf[ks][2], qhf[ks][3], qha + ks * 32);
        ldsm_x4(qlf[ks][0], qlf[ks][1], qlf[ks][2], qlf[ks][3], qla + ks * 32);
    }

    float m[2] = {-1e30f, -1e30f}, l[2] = {0.f, 0.f};
    float O[16][4];
#pragma unroll
    for (int i = 0; i < 16; i++)
#pragma unroll
        for (int e = 0; e < 4; e++) O[i][e] = 0.f;

    const uint32_t koff = ((lane & 7) + ((lane & 16) >> 1)) * AT_SROWB + (((lane >> 3) & 1) << 3) * 2;
    const uint32_t voff = (lane & 15) * AT_SROWB + (((uint32_t)lane >> 4) << 3) * 2;
    const uint32_t ONES = 0x3C003C00u;

    const int nkt = 2 * qt + 2;
    for (int kt = 0; kt < nkt; kt++) {
        const int buf = kt & 1;
        __syncthreads();
        if (kt + 1 < nkt) {
            at_load_kv(sb, buf ^ 1, kt + 1, bh, tid, Kh, Vh);
            CP_WAIT1();
        } else {
            CP_WAIT0();
        }
        __syncthreads();

        // ---- S = Q K^T (2-term: Qh*Kh + Ql*Kh), Q from registers ----
        float sacc[8][4];
#pragma unroll
        for (int nt = 0; nt < 8; nt++)
#pragma unroll
            for (int e = 0; e < 4; e++) sacc[nt][e] = 0.f;

        const uint32_t kbase = sb + SM_K + buf * KPART;
#pragma unroll
        for (int ks = 0; ks < 8; ks++) {
#pragma unroll
            for (int np = 0; np < 4; np++) {
                uint32_t k0r, k1r, k2r, k3r;
                ldsm_x4(k0r, k1r, k2r, k3r,
                        kbase + koff + np * 16 * AT_SROWB + ks * 32);
                mma_f16(sacc[2*np],   qhf[ks], k0r, k1r);
                mma_f16(sacc[2*np],   qlf[ks], k0r, k1r);
                mma_f16(sacc[2*np+1], qhf[ks], k2r, k3r);
                mma_f16(sacc[2*np+1], qlf[ks], k2r, k3r);
            }
        }

        // ---- causal mask (diagonal tiles only) ----
        const int k0 = kt * 64;
        if (k0 + 63 > q0 + w * 16) {
            const int rA = q0 + w * 16 + (lane >> 2);
#pragma unroll
            for (int nt = 0; nt < 8; nt++) {
                int c = k0 + nt * 8 + 2 * (lane & 3);
                if (c     > rA)     sacc[nt][0] = -1e30f;
                if (c + 1 > rA)     sacc[nt][1] = -1e30f;
                if (c     > rA + 8) sacc[nt][2] = -1e30f;
                if (c + 1 > rA + 8) sacc[nt][3] = -1e30f;
            }
        }

        // ---- online softmax (log2 units) ----
        float mx0 = sacc[0][0], mx1 = sacc[0][2];
#pragma unroll
        for (int nt = 0; nt < 8; nt++) {
            mx0 = fmaxf(mx0, fmaxf(sacc[nt][0], sacc[nt][1]));
            mx1 = fmaxf(mx1, fmaxf(sacc[nt][2], sacc[nt][3]));
        }
        mx0 = fmaxf(mx0, __shfl_xor_sync(0xffffffffu, mx0, 1));
        mx0 = fmaxf(mx0, __shfl_xor_sync(0xffffffffu, mx0, 2));
        mx1 = fmaxf(mx1, __shfl_xor_sync(0xffffffffu, mx1, 1));
        mx1 = fmaxf(mx1, __shfl_xor_sync(0xffffffffu, mx1, 2));
        const float mn0 = fmaxf(m[0], mx0), mn1 = fmaxf(m[1], mx1);
        const float fac0 = exp2f(m[0] - mn0), fac1 = exp2f(m[1] - mn1);
        m[0] = mn0; m[1] = mn1;

        // ---- P = 2^(s - mn) as fp16 A-fragments ----
        uint32_t aPh[4][4];
#pragma unroll
        for (int ks = 0; ks < 4; ks++) {
            aPh[ks][0] = ex2_f16x2(sacc[2*ks][0]   - mn0, sacc[2*ks][1]   - mn0);
            aPh[ks][1] = ex2_f16x2(sacc[2*ks][2]   - mn1, sacc[2*ks][3]   - mn1);
            aPh[ks][2] = ex2_f16x2(sacc[2*ks+1][0] - mn0, sacc[2*ks+1][1] - mn0);
            aPh[ks][3] = ex2_f16x2(sacc[2*ks+1][2] - mn1, sacc[2*ks+1][3] - mn1);
        }

        // ---- rescale O; O += P Vh; l via ones-mma ----
#pragma unroll
        for (int i = 0; i < 16; i++) {
            O[i][0] *= fac0; O[i][1] *= fac0;
            O[i][2] *= fac1; O[i][3] *= fac1;
        }
        float Olsum[4] = {0.f, 0.f, 0.f, 0.f};
        const uint32_t vbase = sb + SM_V + buf * KPART;
#pragma unroll
        for (int ks = 0; ks < 4; ks++) {
            mma_f16(Olsum, aPh[ks], ONES, ONES);
#pragma unroll
            for (int dt = 0; dt < 8; dt++) {
                uint32_t va = vbase + voff + ks * 16 * AT_SROWB + dt * 32;
                uint32_t vh0, vh1, vh2, vh3;
                ldsm_x4t(vh0, vh1, vh2, vh3, va);
                mma_f16(O[2*dt],   aPh[ks], vh0, vh1);
                mma_f16(O[2*dt+1], aPh[ks], vh2, vh3);
            }
        }
        l[0] = l[0] * fac0 + Olsum[0];
        l[1] = l[1] * fac1 + Olsum[2];
    }

    // ---- normalize & write fp16 to [b, t, h*128+d] ----
    const float inv0 = 1.f / l[0], inv1 = 1.f / l[1];
    const int rowA = q0 + w * 16 + (lane >> 2);
    const size_t baseA = ((size_t)b * SEQ + rowA) * DMODEL + h * DHEAD;
    const size_t baseB = baseA + (size_t)8 * DMODEL;
#pragma unroll
    for (int nt = 0; nt < 16; nt++) {
        int d = nt * 8 + 2 * (lane & 3);
        __half2 v0 = __floats2half2_rn(O[nt][0] * inv0, O[nt][1] * inv0);
        __half2 v1 = __floats2half2_rn(O[nt][2] * inv1, O[nt][3] * inv1);
        *reinterpret_cast<__half2*>(O16 + baseA + d) = v0;
        *reinterpret_cast<__half2*>(O16 + baseB + d) = v1;
    }
}

// ---------------------------------------------------------------------------
extern "C" void kernel_launch(void* const* d_in, const int* in_sizes, int n_in,
                              void* d_out, int out_size)
{
    const float* x    = (const float*)d_in[0];
    const float* Wqkv = (const float*)d_in[1];
    const float* WO   = (const float*)d_in[2];
    float* out = (float*)d_out;

    float2* rope;
    cudaGetSymbolAddress((void**)&rope, g_rope);
    __half *x16, *wq16, *a16, *wo16;
    cudaGetSymbolAddress((void**)&x16, g_x16);
    cudaGetSymbolAddress((void**)&wq16, g_wq16);
    cudaGetSymbolAddress((void**)&a16, g_a16);
    cudaGetSymbolAddress((void**)&wo16, g_wo16);
    __half *qh16, *ql16, *kh16, *vh16;
    cudaGetSymbolAddress((void**)&qh16, g_qh16); cudaGetSymbolAddress((void**)&ql16, g_ql16);
    cudaGetSymbolAddress((void**)&kh16, g_kh16); cudaGetSymbolAddress((void**)&vh16, g_vh16);

    cudaFuncSetAttribute(gemm_mma, cudaFuncAttributeMaxDynamicSharedMemorySize, GSMEM);
    cudaFuncSetAttribute(gemm_qkv, cudaFuncAttributeMaxDynamicSharedMemorySize, GSMEM);
    cudaFuncSetAttribute(attn_mma, cudaFuncAttributeMaxDynamicSharedMemorySize, AT_SMEM);

    rope_table_kernel<<<(SEQ * 64) / 256, 256>>>(rope);
    { int n4 = (MROWS * KDIM) / 4;
      cvt16_kernel<<<(n4 + 255) / 256, 256>>>((const float4*)x, (uint2*)x16, n4); }
    { int n4 = (QKVDIM * KDIM) / 4;
      cvt16_kernel<<<(n4 + 255) / 256, 256>>>((const float4*)Wqkv, (uint2*)wq16, n4); }
    { int n4 = (DMODEL * KDIM) / 4;
      cvt16_kernel<<<(n4 + 255) / 256, 256>>>((const float4*)WO, (uint2*)wo16, n4); }

    // 1) QKV GEMM with fused RoPE + fp16 pack + [B,H,T,D] transpose
    {
        dim3 grid(QKVDIM / BN, MROWS / BM);
        gemm_qkv<<<grid, 256, GSMEM>>>(x16, wq16, rope, qh16, ql16, kh16, vh16);
    }

    // 2) flash attention -> fp16 (a16)
    {
        dim3 grid(SEQ / 128, NHEADS, BATCH);
        attn_mma<<<grid, 256, AT_SMEM>>>(qh16, ql16, kh16, vh16, a16);
    }

    // 3) out = att @ WO^T
    {
        dim3 grid(DMODEL / BN, MROWS / BM);
        gemm_mma<<<grid, 256, GSMEM>>>(a16, wo16, out, DMODEL);
    }
}

// round 13
// speedup vs baseline: 3.4950x; 1.1357x over previous
#include <cuda_runtime.h>
#include <cuda_bf16.h>
#include <cuda_fp16.h>
#include <math.h>
#include <stdint.h>

// Problem constants
#define BATCH   2
#define SEQ     2048
#define DMODEL  2048
#define NHEADS  16
#define DHEAD   128
#define MROWS   (BATCH*SEQ)          // 4096
#define QKVDIM  (3*DMODEL)           // 6144
#define KDIM    2048

// Scratch (__device__ globals; allocation-free rule)
__device__ float2 g_rope[(size_t)SEQ * 64];
__device__ __half g_x16[(size_t)MROWS * KDIM];
__device__ __half g_wq16[(size_t)QKVDIM * KDIM];
__device__ __half g_a16[(size_t)MROWS * DMODEL];
__device__ __half g_wo16[(size_t)DMODEL * KDIM];
// fp16 attention operands, [B][H][T][D]
#define NATT ((size_t)BATCH * NHEADS * SEQ * DHEAD)
__device__ __half g_qh16[NATT], g_ql16[NATT];
__device__ __half g_kh16[NATT];
__device__ __half g_vh16[NATT];

// ---------------------------------------------------------------------------
// PTX helpers
// ---------------------------------------------------------------------------
static __device__ __forceinline__ uint32_t smem_u32(const void* p) {
    uint32_t a;
    asm("{ .reg .u64 t; cvta.to.shared.u64 t, %1; cvt.u32.u64 %0, t; }" : "=r"(a) : "l"(p));
    return a;
}
static __device__ __forceinline__ void cpasync16(uint32_t dst, const void* src) {
    asm volatile("cp.async.cg.shared.global [%0], [%1], 16;\n" :: "r"(dst), "l"(src));
}
#define CP_COMMIT() asm volatile("cp.async.commit_group;\n" ::: "memory")
#define CP_WAIT0()  asm volatile("cp.async.wait_group 0;\n" ::: "memory")
#define CP_WAIT1()  asm volatile("cp.async.wait_group 1;\n" ::: "memory")

static __device__ __forceinline__ void ldsm_x4(uint32_t& r0, uint32_t& r1,
                                               uint32_t& r2, uint32_t& r3, uint32_t a) {
    asm volatile("ldmatrix.sync.aligned.m8n8.x4.shared.b16 {%0,%1,%2,%3}, [%4];"
                 : "=r"(r0), "=r"(r1), "=r"(r2), "=r"(r3) : "r"(a));
}
static __device__ __forceinline__ void ldsm_x4t(uint32_t& r0, uint32_t& r1,
                                                uint32_t& r2, uint32_t& r3, uint32_t a) {
    asm volatile("ldmatrix.sync.aligned.m8n8.x4.trans.shared.b16 {%0,%1,%2,%3}, [%4];"
                 : "=r"(r0), "=r"(r1), "=r"(r2), "=r"(r3) : "r"(a));
}
static __device__ __forceinline__ void mma_f16(float* c, const uint32_t* a,
                                               uint32_t b0, uint32_t b1) {
    asm volatile(
        "mma.sync.aligned.m16n8k16.row.col.f32.f16.f16.f32 "
        "{%0,%1,%2,%3}, {%4,%5,%6,%7}, {%8,%9}, {%0,%1,%2,%3};"
        : "+f"(c[0]), "+f"(c[1]), "+f"(c[2]), "+f"(c[3])
        : "r"(a[0]), "r"(a[1]), "r"(a[2]), "r"(a[3]), "r"(b0), "r"(b1));
}
static __device__ __forceinline__ void pack_hl(float f0, float f1, uint32_t& hi, uint32_t& lo) {
    __half2 h = __floats2half2_rn(f0, f1);
    float2 fb = __half22float2(h);
    __half2 l2 = __floats2half2_rn(f0 - fb.x, f1 - fb.y);
    hi = *reinterpret_cast<uint32_t*>(&h);
    lo = *reinterpret_cast<uint32_t*>(&l2);
}
static __device__ __forceinline__ uint32_t ex2_f16x2(float a, float b) {
    uint32_t d;
    asm("{ .reg .b32 t;\n cvt.rn.f16x2.f32 t, %2, %1;\n ex2.approx.f16x2 %0, t;\n}"
        : "=r"(d) : "f"(a), "f"(b));
    return d;
}

// ---------------------------------------------------------------------------
// fp32 -> fp16, vectorized x4
// ---------------------------------------------------------------------------
__global__ __launch_bounds__(256) void cvt16_kernel(
    const float4* __restrict__ s, uint2* __restrict__ d, int n4)
{
    int i = blockIdx.x * 256 + threadIdx.x;
    if (i >= n4) return;
    float4 v = s[i];
    __half2 h01 = __floats2half2_rn(v.x, v.y);
    __half2 h23 = __floats2half2_rn(v.z, v.w);
    uint2 dv;
    dv.x = *reinterpret_cast<uint32_t*>(&h01); dv.y = *reinterpret_cast<uint32_t*>(&h23);
    d[i] = dv;
}

// ---------------------------------------------------------------------------
// RoPE cos/sin table
// ---------------------------------------------------------------------------
__global__ __launch_bounds__(256) void rope_table_kernel(float2* __restrict__ tab)
{
    int idx = blockIdx.x * 256 + threadIdx.x;
    int i = idx & 63, t = idx >> 6;
    double freq = exp(-9.210340371976184 * (double)(2 * i) / 128.0);
    double sd, cd;
    sincos((double)t * freq, &sd, &cd);
    tab[idx] = make_float2((float)cd, (float)sd);
}

// ---------------------------------------------------------------------------
// GEMM mainloop (NT, fp16: C = A * B^T), BK=64 double-buffered, occ 2.
// BM=BN=128, 256 threads, 8 warps (2m x 4n), warp tile 64x32.
// Row stride 72 halves (144B): 8-row ldsm phases land on distinct 16B units.
// ---------------------------------------------------------------------------
#define BM 128
#define BN 128
#define BK 64
#define SROW 72
#define PART_BYTES (128 * SROW * 2)          // 18432
#define A_OFF 0
#define B_OFF PART_BYTES
#define STG_BYTES (2 * PART_BYTES)           // 36864
#define GSMEM (2 * STG_BYTES)                // 73728

static __device__ __forceinline__ void g_load_stage(
    uint32_t sb, int buf, int s, int bm, int bn, int tid,
    const __half* __restrict__ A, const __half* __restrict__ B)
{
    uint32_t base = sb + buf * STG_BYTES;
    const int k0 = s * BK;
    // 2048 16B-chunks: A [0,1024), B [1024,2048); 8 chunks per 64-half row.
#pragma unroll
    for (int it = 0; it < 8; it++) {
        int idx = tid + it * 256;
        int part = idx >> 10;                // uniform per it
        int rem = idx & 1023;
        int r = rem >> 3, ch = rem & 7;
        const __half* src = part ? B : A;
        int row = part ? (bn + r) : (bm + r);
        cpasync16(base + part * PART_BYTES + r * (SROW * 2) + ch * 16,
                  src + (size_t)row * KDIM + k0 + ch * 8);
    }
    CP_COMMIT();
}

static __device__ __forceinline__ void g_mainloop(
    uint32_t sb, int bm, int bn, int tid, int lane, int wm, int wn,
    const __half* __restrict__ A, const __half* __restrict__ B,
    float acc[4][4][4])
{
    const uint32_t aRow = wm * 64 + (lane & 15);
    const uint32_t aCol = (lane >> 4) << 3;
    const uint32_t bOff = (wn * 32 + (lane & 7) + ((lane & 16) >> 1)) * (SROW * 2)
                        + (((lane >> 3) & 1) << 3) * 2;

    g_load_stage(sb, 0, 0, bm, bn, tid, A, B);

    const int NS = KDIM / BK;                // 32
    for (int s = 0; s < NS; s++) {
        const int buf = s & 1;
        if (s + 1 < NS) {
            g_load_stage(sb, buf ^ 1, s + 1, bm, bn, tid, A, B);
            CP_WAIT1();
        } else {
            CP_WAIT0();
        }
        __syncthreads();

        uint32_t base = sb + buf * STG_BYTES;
#pragma unroll
        for (int kk = 0; kk < BK; kk += 16) {
            uint32_t af[4][4], bf[4][2];
#pragma unroll
            for (int mt = 0; mt < 4; mt++)
                ldsm_x4(af[mt][0], af[mt][1], af[mt][2], af[mt][3],
                        base + A_OFF + (aRow + mt * 16) * (SROW * 2) + (aCol + kk) * 2);
#pragma unroll
            for (int np = 0; np < 2; np++)
                ldsm_x4(bf[2*np][0], bf[2*np][1], bf[2*np+1][0], bf[2*np+1][1],
                        base + B_OFF + bOff + np * 16 * (SROW * 2) + kk * 2);
#pragma unroll
            for (int mt = 0; mt < 4; mt++)
#pragma unroll
                for (int nt = 0; nt < 4; nt++)
                    mma_f16(acc[mt][nt], af[mt], bf[nt][0], bf[nt][1]);
        }
        __syncthreads();
    }
}

// Plain fp32-output GEMM (WO projection)
__global__ __launch_bounds__(256, 2) void gemm_mma(
    const __half* __restrict__ A, const __half* __restrict__ B,
    float* __restrict__ C, int ldc)
{
    extern __shared__ char smem[];
    uint32_t sb = smem_u32(smem);
    const int tid = threadIdx.x, wid = tid >> 5, lane = tid & 31;
    const int wm = wid >> 2, wn = wid & 3;
    const int bm = blockIdx.y * BM, bn = blockIdx.x * BN;

    float acc[4][4][4];
#pragma unroll
    for (int i = 0; i < 4; i++)
#pragma unroll
        for (int j = 0; j < 4; j++)
#pragma unroll
            for (int e = 0; e < 4; e++) acc[i][j][e] = 0.f;

    g_mainloop(sb, bm, bn, tid, lane, wm, wn, A, B, acc);

    const int r0 = bm + wm * 64 + (lane >> 2);
    const int c0 = bn + wn * 32 + 2 * (lane & 3);
#pragma unroll
    for (int mt = 0; mt < 4; mt++)
#pragma unroll
        for (int nt = 0; nt < 4; nt++) {
            float2 v0 = make_float2(acc[mt][nt][0], acc[mt][nt][1]);
            float2 v1 = make_float2(acc[mt][nt][2], acc[mt][nt][3]);
            *reinterpret_cast<float2*>(&C[(size_t)(r0 + mt * 16)     * ldc + c0 + nt * 8]) = v0;
            *reinterpret_cast<float2*>(&C[(size_t)(r0 + mt * 16 + 8) * ldc + c0 + nt * 8]) = v1;
        }
}

// QKV GEMM with fused RoPE + fp16 pack + [B,H,T,D] transpose epilogue.
__global__ __launch_bounds__(256, 2) void gemm_qkv(
    const __half* __restrict__ A, const __half* __restrict__ B,
    const float2* __restrict__ tab,
    __half* __restrict__ Qh, __half* __restrict__ Ql,
    __half* __restrict__ Kh, __half* __restrict__ Vh)
{
    extern __shared__ char smem[];
    uint32_t sb = smem_u32(smem);
    const int tid = threadIdx.x, wid = tid >> 5, lane = tid & 31;
    const int wm = wid >> 2, wn = wid & 3;
    const int bm = blockIdx.y * BM, bn = blockIdx.x * BN;

    float acc[4][4][4];
#pragma unroll
    for (int i = 0; i < 4; i++)
#pragma unroll
        for (int j = 0; j < 4; j++)
#pragma unroll
            for (int e = 0; e < 4; e++) acc[i][j][e] = 0.f;

    g_mainloop(sb, bm, bn, tid, lane, wm, wn, A, B, acc);

    const int mat  = bn >> 11;                  // 0=Q,1=K,2=V
    const int head = (bn >> 7) & (NHEADS - 1);
    const float QSCL = 0.1275174456f;           // log2(e)/sqrt(128)

    const int r0 = bm + wm * 64 + (lane >> 2);
    const int c0 = (bn & 127) + wn * 32 + 2 * (lane & 3);
    const int b  = r0 >> 11;
    const size_t obase = ((size_t)(b * NHEADS + head)) * SEQ * DHEAD;

#pragma unroll
    for (int mt = 0; mt < 4; mt++) {
        const int tA = (r0 + mt * 16) & (SEQ - 1);
        const int tB = tA + 8;
#pragma unroll
        for (int nt = 0; nt < 4; nt++) {
            const int d = c0 + nt * 8;
            float x0 = acc[mt][nt][0], x1 = acc[mt][nt][1];
            float y0 = acc[mt][nt][2], y1 = acc[mt][nt][3];
            if (mat < 2) {
                float2 csA = tab[tA * 64 + (d >> 1)];
                float2 csB = tab[tB * 64 + (d >> 1)];
                float nx0 = x0 * csA.x - x1 * csA.y;
                float nx1 = x1 * csA.x + x0 * csA.y;
                float ny0 = y0 * csB.x - y1 * csB.y;
                float ny1 = y1 * csB.x + y0 * csB.y;
                x0 = nx0; x1 = nx1; y0 = ny0; y1 = ny1;
                if (mat == 0) { x0 *= QSCL; x1 *= QSCL; y0 *= QSCL; y1 *= QSCL; }
            }
            size_t dA = obase + (size_t)tA * DHEAD + d;
            size_t dB = obase + (size_t)tB * DHEAD + d;
            if (mat == 0) {
                uint32_t hi, lo;
                pack_hl(x0, x1, hi, lo);
                *reinterpret_cast<uint32_t*>(Qh + dA) = hi;
                *reinterpret_cast<uint32_t*>(Ql + dA) = lo;
                pack_hl(y0, y1, hi, lo);
                *reinterpret_cast<uint32_t*>(Qh + dB) = hi;
                *reinterpret_cast<uint32_t*>(Ql + dB) = lo;
            } else {
                __half* D = (mat == 1) ? Kh : Vh;
                __half2 v0 = __floats2half2_rn(x0, x1);
                __half2 v1 = __floats2half2_rn(y0, y1);
                *reinterpret_cast<__half2*>(D + dA) = v0;
                *reinterpret_cast<__half2*>(D + dB) = v1;
            }
        }
    }
}

// ---------------------------------------------------------------------------
// Flash attention. Q loaded direct global->registers (mma A-frag addressing);
// KV double-buffered in smem (unchanged structure). TQ=128, TK=64, 8 warps.
// ---------------------------------------------------------------------------
#define AT_SROWB 272
#define SM_K  0
#define SM_V  34816
#define KPART 17408
#define AT_SMEM 69632

static __device__ __forceinline__ void at_load_kv(
    uint32_t sb, int buf, int kt, size_t bh, int tid,
    const __half* __restrict__ Kh, const __half* __restrict__ Vh)
{
    const int k0 = kt * 64;
#pragma unroll
    for (int it = 0; it < 8; it++) {
        int idx = tid + it * 256;
        int part = idx >> 10;               // 0:Kh 1:Vh
        int rem = idx & 1023;
        int r = rem >> 4, ch = rem & 15;
        const __half* src = (part == 0) ? Kh : Vh;
        uint32_t dbase = ((part == 0) ? SM_K : SM_V) + buf * KPART;
        cpasync16(sb + dbase + r * AT_SROWB + ch * 16,
                  src + ((size_t)(bh + k0 + r)) * DHEAD + ch * 8);
    }
    CP_COMMIT();
}

__global__ __launch_bounds__(256, 1) void attn_mma(
    const __half* __restrict__ Qh, const __half* __restrict__ Ql,
    const __half* __restrict__ Kh, const __half* __restrict__ Vh,
    __half* __restrict__ O16)
{
    extern __shared__ char smem[];
    uint32_t sb = smem_u32(smem);
    const int tid = threadIdx.x, lane = tid & 31, w = tid >> 5;
    const int qt = gridDim.x - 1 - blockIdx.x;
    const int h = blockIdx.y, b = blockIdx.z;
    const int q0 = qt * 128;
    const size_t bh = (size_t)(b * NHEADS + h) * SEQ;

    at_load_kv(sb, 0, 0, bh, tid, Kh, Vh);

    // Q fragments straight from global into registers.
    // a-frag element map: reg0=(r,c), reg1=(r+8,c), reg2=(r,c+8), reg3=(r+8,c+8)
    uint32_t qhf[8][4], qlf[8][4];
    {
        const size_t rowbase = (bh + q0 + w * 16 + (lane >> 2)) * (size_t)DHEAD
                             + 2 * (lane & 3);
        const __half* ph = Qh + rowbase;
        const __half* pl = Ql + rowbase;
#pragma unroll
        for (int ks = 0; ks < 8; ks++) {
            int c = ks * 16;
            qhf[ks][0] = *reinterpret_cast<const uint32_t*>(ph + c);
            qhf[ks][1] = *reinterpret_cast<const uint32_t*>(ph + 8 * DHEAD + c);
            qhf[ks][2] = *reinterpret_cast<const uint32_t*>(ph + c + 8);
            qhf[ks][3] = *reinterpret_cast<const uint32_t*>(ph + 8 * DHEAD + c + 8);
            qlf[ks][0] = *reinterpret_cast<const uint32_t*>(pl + c);
            qlf[ks][1] = *reinterpret_cast<const uint32_t*>(pl + 8 * DHEAD + c);
            qlf[ks][2] = *reinterpret_cast<const uint32_t*>(pl + c + 8);
            qlf[ks][3] = *reinterpret_cast<const uint32_t*>(pl + 8 * DHEAD + c + 8);
        }
    }

    float m[2] = {-1e30f, -1e30f}, l[2] = {0.f, 0.f};
    float O[16][4];
#pragma unroll
    for (int i = 0; i < 16; i++)
#pragma unroll
        for (int e = 0; e < 4; e++) O[i][e] = 0.f;

    const uint32_t koff = ((lane & 7) + ((lane & 16) >> 1)) * AT_SROWB + (((lane >> 3) & 1) << 3) * 2;
    const uint32_t voff = (lane & 15) * AT_SROWB + (((uint32_t)lane >> 4) << 3) * 2;
    const uint32_t ONES = 0x3C003C00u;

    const int nkt = 2 * qt + 2;
    for (int kt = 0; kt < nkt; kt++) {
        const int buf = kt & 1;
        __syncthreads();
        if (kt + 1 < nkt) {
            at_load_kv(sb, buf ^ 1, kt + 1, bh, tid, Kh, Vh);
            CP_WAIT1();
        } else {
            CP_WAIT0();
        }
        __syncthreads();

        // ---- S = Q K^T (2-term: Qh*Kh + Ql*Kh), Q from registers ----
        float sacc[8][4];
#pragma unroll
        for (int nt = 0; nt < 8; nt++)
#pragma unroll
            for (int e = 0; e < 4; e++) sacc[nt][e] = 0.f;

        const uint32_t kbase = sb + SM_K + buf * KPART;
#pragma unroll
        for (int ks = 0; ks < 8; ks++) {
#pragma unroll
            for (int np = 0; np < 4; np++) {
                uint32_t k0r, k1r, k2r, k3r;
                ldsm_x4(k0r, k1r, k2r, k3r,
                        kbase + koff + np * 16 * AT_SROWB + ks * 32);
                mma_f16(sacc[2*np],   qhf[ks], k0r, k1r);
                mma_f16(sacc[2*np],   qlf[ks], k0r, k1r);
                mma_f16(sacc[2*np+1], qhf[ks], k2r, k3r);
                mma_f16(sacc[2*np+1], qlf[ks], k2r, k3r);
            }
        }

        // ---- causal mask (diagonal tiles only) ----
        const int k0 = kt * 64;
        if (k0 + 63 > q0 + w * 16) {
            const int rA = q0 + w * 16 + (lane >> 2);
#pragma unroll
            for (int nt = 0; nt < 8; nt++) {
                int c = k0 + nt * 8 + 2 * (lane & 3);
                if (c     > rA)     sacc[nt][0] = -1e30f;
                if (c + 1 > rA)     sacc[nt][1] = -1e30f;
                if (c     > rA + 8) sacc[nt][2] = -1e30f;
                if (c + 1 > rA + 8) sacc[nt][3] = -1e30f;
            }
        }

        // ---- online softmax (log2 units) ----
        float mx0 = sacc[0][0], mx1 = sacc[0][2];
#pragma unroll
        for (int nt = 0; nt < 8; nt++) {
            mx0 = fmaxf(mx0, fmaxf(sacc[nt][0], sacc[nt][1]));
            mx1 = fmaxf(mx1, fmaxf(sacc[nt][2], sacc[nt][3]));
        }
        mx0 = fmaxf(mx0, __shfl_xor_sync(0xffffffffu, mx0, 1));
        mx0 = fmaxf(mx0, __shfl_xor_sync(0xffffffffu, mx0, 2));
        mx1 = fmaxf(mx1, __shfl_xor_sync(0xffffffffu, mx1, 1));
        mx1 = fmaxf(mx1, __shfl_xor_sync(0xffffffffu, mx1, 2));
        const float mn0 = fmaxf(m[0], mx0), mn1 = fmaxf(m[1], mx1);
        const float fac0 = exp2f(m[0] - mn0), fac1 = exp2f(m[1] - mn1);
        m[0] = mn0; m[1] = mn1;

        // ---- P = 2^(s - mn) as fp16 A-fragments ----
        uint32_t aPh[4][4];
#pragma unroll
        for (int ks = 0; ks < 4; ks++) {
            aPh[ks][0] = ex2_f16x2(sacc[2*ks][0]   - mn0, sacc[2*ks][1]   - mn0);
            aPh[ks][1] = ex2_f16x2(sacc[2*ks][2]   - mn1, sacc[2*ks][3]   - mn1);
            aPh[ks][2] = ex2_f16x2(sacc[2*ks+1][0] - mn0, sacc[2*ks+1][1] - mn0);
            aPh[ks][3] = ex2_f16x2(sacc[2*ks+1][2] - mn1, sacc[2*ks+1][3] - mn1);
        }

        // ---- rescale O; O += P Vh; l via ones-mma ----
#pragma unroll
        for (int i = 0; i < 16; i++) {
            O[i][0] *= fac0; O[i][1] *= fac0;
            O[i][2] *= fac1; O[i][3] *= fac1;
        }
        float Olsum[4] = {0.f, 0.f, 0.f, 0.f};
        const uint32_t vbase = sb + SM_V + buf * KPART;
#pragma unroll
        for (int ks = 0; ks < 4; ks++) {
            mma_f16(Olsum, aPh[ks], ONES, ONES);
#pragma unroll
            for (int dt = 0; dt < 8; dt++) {
                uint32_t va = vbase + voff + ks * 16 * AT_SROWB + dt * 32;
                uint32_t vh0, vh1, vh2, vh3;
                ldsm_x4t(vh0, vh1, vh2, vh3, va);
                mma_f16(O[2*dt],   aPh[ks], vh0, vh1);
                mma_f16(O[2*dt+1], aPh[ks], vh2, vh3);
            }
        }
        l[0] = l[0] * fac0 + Olsum[0];
        l[1] = l[1] * fac1 + Olsum[2];
    }

    // ---- normalize & write fp16 to [b, t, h*128+d] ----
    const float inv0 = 1.f / l[0], inv1 = 1.f / l[1];
    const int rowA = q0 + w * 16 + (lane >> 2);
    const size_t baseA = ((size_t)b * SEQ + rowA) * DMODEL + h * DHEAD;
    const size_t baseB = baseA + (size_t)8 * DMODEL;
#pragma unroll
    for (int nt = 0; nt < 16; nt++) {
        int d = nt * 8 + 2 * (lane & 3);
        __half2 v0 = __floats2half2_rn(O[nt][0] * inv0, O[nt][1] * inv0);
        __half2 v1 = __floats2half2_rn(O[nt][2] * inv1, O[nt][3] * inv1);
        *reinterpret_cast<__half2*>(O16 + baseA + d) = v0;
        *reinterpret_cast<__half2*>(O16 + baseB + d) = v1;
    }
}

// ---------------------------------------------------------------------------
extern "C" void kernel_launch(void* const* d_in, const int* in_sizes, int n_in,
                              void* d_out, int out_size)
{
    const float* x    = (const float*)d_in[0];
    const float* Wqkv = (const float*)d_in[1];
    const float* WO   = (const float*)d_in[2];
    float* out = (float*)d_out;

    float2* rope;
    cudaGetSymbolAddress((void**)&rope, g_rope);
    __half *x16, *wq16, *a16, *wo16;
    cudaGetSymbolAddress((void**)&x16, g_x16);
    cudaGetSymbolAddress((void**)&wq16, g_wq16);
    cudaGetSymbolAddress((void**)&a16, g_a16);
    cudaGetSymbolAddress((void**)&wo16, g_wo16);
    __half *qh16, *ql16, *kh16, *vh16;
    cudaGetSymbolAddress((void**)&qh16, g_qh16); cudaGetSymbolAddress((void**)&ql16, g_ql16);
    cudaGetSymbolAddress((void**)&kh16, g_kh16); cudaGetSymbolAddress((void**)&vh16, g_vh16);

    cudaFuncSetAttribute(gemm_mma, cudaFuncAttributeMaxDynamicSharedMemorySize, GSMEM);
    cudaFuncSetAttribute(gemm_qkv, cudaFuncAttributeMaxDynamicSharedMemorySize, GSMEM);
    cudaFuncSetAttribute(attn_mma, cudaFuncAttributeMaxDynamicSharedMemorySize, AT_SMEM);

    rope_table_kernel<<<(SEQ * 64) / 256, 256>>>(rope);
    { int n4 = (MROWS * KDIM) / 4;
      cvt16_kernel<<<(n4 + 255) / 256, 256>>>((const float4*)x, (uint2*)x16, n4); }
    { int n4 = (QKVDIM * KDIM) / 4;
      cvt16_kernel<<<(n4 + 255) / 256, 256>>>((const float4*)Wqkv, (uint2*)wq16, n4); }
    { int n4 = (DMODEL * KDIM) / 4;
      cvt16_kernel<<<(n4 + 255) / 256, 256>>>((const float4*)WO, (uint2*)wo16, n4); }

    // 1) QKV GEMM with fused RoPE + fp16 pack + [B,H,T,D] transpose
    {
        dim3 grid(QKVDIM / BN, MROWS / BM);
        gemm_qkv<<<grid, 256, GSMEM>>>(x16, wq16, rope, qh16, ql16, kh16, vh16);
    }

    // 2) flash attention -> fp16 (a16)
    {
        dim3 grid(SEQ / 128, NHEADS, BATCH);
        attn_mma<<<grid, 256, AT_SMEM>>>(qh16, ql16, kh16, vh16, a16);
    }

    // 3) out = att @ WO^T
    {
        dim3 grid(DMODEL / BN, MROWS / BM);
        gemm_mma<<<grid, 256, GSMEM>>>(a16, wo16, out, DMODEL);
    }
}